// round 4
// baseline (speedup 1.0000x reference)
#include <cuda_runtime.h>
#include <cuda_bf16.h>

#define N_UE 100000
#define N_AP 10000
#define N_E  1600000
#define DD   64
#define HH   128
#define TILES (N_E / 128)          // 12500
#define PGRID 296                  // 2 blocks/SM * 148 SMs

// ---------------- scratch (device globals; no allocation allowed) ----------
__device__ float g_ueproj[(size_t)N_UE * HH];      // ue_hid @ W1a[64:] + b1a
__device__ float g_agg[(size_t)N_AP * HH];         // segment_sum(relu(...))
__device__ int   g_cnt[N_AP];
__device__ int   g_cursor[N_AP];
__device__ int4  g_meta[N_E];                      // (edge_idx, src, dst, 0) sorted by dst
__device__ __nv_bfloat16 g_wt_hi[HH * DD];         // W1a[:64] transposed [n][k], bf16 hi
__device__ __nv_bfloat16 g_wt_lo[HH * DD];         // residual lo plane

// ---------------- small setup kernels --------------------------------------
__global__ void k_zero() {
    int i = blockIdx.x * 256 + threadIdx.x;
    if (i < N_AP * HH) g_agg[i] = 0.f;
    if (i < N_AP) g_cnt[i] = 0;
}

__global__ void k_hist(const int* __restrict__ dst) {
    int i = blockIdx.x * 256 + threadIdx.x;
    if (i < N_E) atomicAdd(&g_cnt[dst[i]], 1);
}

// block 0: exclusive prefix over 10000 bins -> g_cursor.
// blocks 1..8: prepare bf16 split weight planes.
__global__ void k_scan_prep(const float* __restrict__ W1a) {
    if (blockIdx.x == 0) {
        __shared__ int buf[1024];
        int t = threadIdx.x;
        int local[16];
        int s = 0;
        if (t < 625) {
            #pragma unroll
            for (int j = 0; j < 16; j++) { local[j] = s; s += g_cnt[t * 16 + j]; }
        }
        buf[t] = s;
        __syncthreads();
        int own = s;
        for (int off = 1; off < 1024; off <<= 1) {
            int v = 0;
            if (t >= off) v = buf[t - off];
            __syncthreads();
            buf[t] += v;
            __syncthreads();
        }
        int excl = buf[t] - own;
        if (t < 625) {
            #pragma unroll
            for (int j = 0; j < 16; j++) g_cursor[t * 16 + j] = excl + local[j];
        }
    } else {
        int j = (blockIdx.x - 1) * 1024 + threadIdx.x;
        if (j < HH * DD) {
            int n = j >> 6, k = j & 63;                 // Wt[n][k] = W1a[k][n]
            float v = W1a[k * HH + n];
            __nv_bfloat16 h = __float2bfloat16(v);
            g_wt_hi[j] = h;
            g_wt_lo[j] = __float2bfloat16(v - __bfloat162float(h));
        }
    }
}

__global__ void k_scatter(const int* __restrict__ src, const int* __restrict__ dst) {
    int i = blockIdx.x * 256 + threadIdx.x;
    if (i < N_E) {
        int d = dst[i];
        int p = atomicAdd(&g_cursor[d], 1);
        g_meta[p] = make_int4(i, src[i], d, 0);
    }
}

// ---------------- ue projection: g_ueproj = ue_hid @ W1a[64:128] + b1a -----
__global__ void __launch_bounds__(256) k_ueproj(
    const float* __restrict__ ue_hid, const float* __restrict__ W1a,
    const float* __restrict__ b1a)
{
    __shared__ float us[64][64];
    int t = threadIdx.x;
    int rbase = blockIdx.x * 64;

    for (int f = t; f < 1024; f += 256) {
        int row = f >> 4, c4 = f & 15;
        float4 v = make_float4(0.f, 0.f, 0.f, 0.f);
        if (rbase + row < N_UE)
            v = *(const float4*)(ue_hid + (size_t)(rbase + row) * DD + c4 * 4);
        *(float4*)(&us[row][c4 * 4]) = v;
    }

    int c = t & 127;
    int rh = t >> 7;
    float wc[64];
    #pragma unroll 8
    for (int k = 0; k < 64; k++) wc[k] = W1a[(64 + k) * HH + c];
    float bb = b1a[c];
    __syncthreads();

    for (int i = 0; i < 32; i++) {
        int r = rh * 32 + i;
        int gr = rbase + r;
        if (gr >= N_UE) break;          // uniform per warp
        float acc = bb;
        #pragma unroll
        for (int k4 = 0; k4 < 16; k4++) {
            float4 u4 = *(const float4*)(&us[r][k4 * 4]);
            acc += u4.x * wc[k4 * 4 + 0];
            acc += u4.y * wc[k4 * 4 + 1];
            acc += u4.z * wc[k4 * 4 + 2];
            acc += u4.w * wc[k4 * 4 + 3];
        }
        g_ueproj[(size_t)gr * HH + c] = acc;
    }
}

// ---------------- main edge kernel: persistent, bf16-split mma -------------
__device__ __forceinline__ void mma_bf16(float c[4],
    unsigned a0, unsigned a1, unsigned a2, unsigned a3,
    unsigned b0, unsigned b1)
{
    asm volatile(
        "mma.sync.aligned.m16n8k16.row.col.f32.bf16.bf16.f32 "
        "{%0,%1,%2,%3}, {%4,%5,%6,%7}, {%8,%9}, {%0,%1,%2,%3};\n"
        : "+f"(c[0]), "+f"(c[1]), "+f"(c[2]), "+f"(c[3])
        : "r"(a0), "r"(a1), "r"(a2), "r"(a3), "r"(b0), "r"(b1));
}

#define ASTR 72                          // padded smem stride (bf16 elems)
#define HSTR 66                          // Hs stride (floats), per 64-col pass
#define SMEM_MAIN (4 * 128 * ASTR * 2)   // 73728 B; Hs (33792 B) overlays A region

__global__ void __launch_bounds__(256, 2) k_main(const float* __restrict__ edge_hid)
{
    extern __shared__ char sraw[];
    __nv_bfloat16* Ah = (__nv_bfloat16*)sraw;          // [128][72]
    __nv_bfloat16* Al = Ah + 128 * ASTR;
    __nv_bfloat16* Bh = Al + 128 * ASTR;               // Wt [n=128][k=64], persistent
    __nv_bfloat16* Bl = Bh + 128 * ASTR;
    float* Hs = (float*)sraw;                          // [128][66], overlays Ah/Al
    __shared__ int s_src[128];
    __shared__ int s_dst[128];

    int t = threadIdx.x;
    int w = t >> 5, l = t & 31;
    int g = l >> 2, q4 = l & 3;
    int ar = w * 16 + g;                 // warp w owns rows [16w,16w+16)

    // stage weights ONCE per persistent block
    for (int j = t; j < HH * DD; j += 256) {
        int n = j >> 6, k = j & 63;
        Bh[n * ASTR + k] = g_wt_hi[j];
        Bl[n * ASTR + k] = g_wt_lo[j];
    }
    // (covered by the sync inside the first tile iteration)

    for (int tile = blockIdx.x; tile < TILES; tile += gridDim.x) {
        int base = tile * 128;

        __syncthreads();   // prev tile's Hs/s_dst consumers done; weights staged (1st iter)

        // meta -> smem, and gather+convert 128 edge rows (row = t>>1, half = t&1)
        if (t < 128) {
            int4 m = g_meta[base + t];
            s_src[t] = m.y;
            s_dst[t] = m.z;
        }
        {
            int row = t >> 1, half = t & 1;
            int e = g_meta[base + row].x;
            const float4* src4 = (const float4*)(edge_hid + (size_t)e * DD + half * 32);
            int sb = row * ASTR + half * 32;
            #pragma unroll
            for (int q = 0; q < 8; q++) {
                float4 v = src4[q];
                __nv_bfloat162 h01 = __floats2bfloat162_rn(v.x, v.y);
                __nv_bfloat162 h23 = __floats2bfloat162_rn(v.z, v.w);
                float2 f01 = __bfloat1622float2(h01);
                float2 f23 = __bfloat1622float2(h23);
                __nv_bfloat162 l01 = __floats2bfloat162_rn(v.x - f01.x, v.y - f01.y);
                __nv_bfloat162 l23 = __floats2bfloat162_rn(v.z - f23.x, v.w - f23.y);
                *(__nv_bfloat162*)(Ah + sb + q * 4)     = h01;
                *(__nv_bfloat162*)(Ah + sb + q * 4 + 2) = h23;
                *(__nv_bfloat162*)(Al + sb + q * 4)     = l01;
                *(__nv_bfloat162*)(Al + sb + q * 4 + 2) = l23;
            }
        }
        __syncthreads();

        float C[16][4];
        #pragma unroll
        for (int nf = 0; nf < 16; nf++) { C[nf][0] = C[nf][1] = C[nf][2] = C[nf][3] = 0.f; }

        #pragma unroll
        for (int kt = 0; kt < 4; kt++) {
            int k0 = kt * 16 + q4 * 2;
            unsigned ah0 = *(const unsigned*)(Ah + ar * ASTR + k0);
            unsigned ah1 = *(const unsigned*)(Ah + (ar + 8) * ASTR + k0);
            unsigned ah2 = *(const unsigned*)(Ah + ar * ASTR + k0 + 8);
            unsigned ah3 = *(const unsigned*)(Ah + (ar + 8) * ASTR + k0 + 8);
            unsigned al0 = *(const unsigned*)(Al + ar * ASTR + k0);
            unsigned al1 = *(const unsigned*)(Al + (ar + 8) * ASTR + k0);
            unsigned al2 = *(const unsigned*)(Al + ar * ASTR + k0 + 8);
            unsigned al3 = *(const unsigned*)(Al + (ar + 8) * ASTR + k0 + 8);
            #pragma unroll
            for (int nf = 0; nf < 16; nf++) {
                int n = nf * 8 + g;
                unsigned bh0 = *(const unsigned*)(Bh + n * ASTR + k0);
                unsigned bh1 = *(const unsigned*)(Bh + n * ASTR + k0 + 8);
                unsigned bl0 = *(const unsigned*)(Bl + n * ASTR + k0);
                unsigned bl1 = *(const unsigned*)(Bl + n * ASTR + k0 + 8);
                mma_bf16(C[nf], ah0, ah1, ah2, ah3, bh0, bh1);   // hi*hi
                mma_bf16(C[nf], ah0, ah1, ah2, ah3, bl0, bl1);   // hi*lo
                mma_bf16(C[nf], al0, al1, al2, al3, bh0, bh1);   // lo*hi
            }
        }
        __syncthreads();   // A/B(A-part) reads done -> Hs may overwrite A region

        int s0 = s_src[ar], s1 = s_src[ar + 8];
        const float* up0 = g_ueproj + (size_t)s0 * HH;
        const float* up1 = g_ueproj + (size_t)s1 * HH;

        #pragma unroll
        for (int pass = 0; pass < 2; pass++) {
            // epilogue: + ue_proj[src] gather, relu, stage 64 columns to Hs
            #pragma unroll
            for (int nfl = 0; nfl < 8; nfl++) {
                int nf = pass * 8 + nfl;
                int c0 = nf * 8 + q4 * 2;       // global column
                int lc = c0 - pass * 64;        // local column in Hs
                float2 u0 = *(const float2*)(up0 + c0);
                float2 u1 = *(const float2*)(up1 + c0);
                float2 v0, v1;
                v0.x = fmaxf(C[nf][0] + u0.x, 0.f);
                v0.y = fmaxf(C[nf][1] + u0.y, 0.f);
                v1.x = fmaxf(C[nf][2] + u1.x, 0.f);
                v1.y = fmaxf(C[nf][3] + u1.y, 0.f);
                *(float2*)(Hs + ar * HSTR + lc) = v0;
                *(float2*)(Hs + (ar + 8) * HSTR + lc) = v1;
            }
            __syncthreads();

            // segmented reduce over sorted dst: 4 row-quarters x 64 cols
            {
                int cl = t & 63, qr = t >> 6;
                int r0 = qr * 32;
                float acc = 0.f;
                int prev = s_dst[r0];
                #pragma unroll 4
                for (int i = 0; i < 32; i++) {
                    int r = r0 + i;
                    int d = s_dst[r];
                    if (d != prev) {
                        atomicAdd(&g_agg[(size_t)prev * HH + pass * 64 + cl], acc);
                        acc = 0.f; prev = d;
                    }
                    acc += Hs[r * HSTR + cl];
                }
                atomicAdd(&g_agg[(size_t)prev * HH + pass * 64 + cl], acc);
            }
            if (pass == 0) __syncthreads();   // Hs readers done before pass-2 writes
        }
    }
}

// ---------------- final AP MLP: agg@W1b + deg*b1b, concat, mlp2 ------------
__global__ void __launch_bounds__(128) k_final(
    const float* __restrict__ ap_hid,
    const float* __restrict__ W1b, const float* __restrict__ b1b,
    const float* __restrict__ W2a, const float* __restrict__ b2a,
    const float* __restrict__ W2b, const float* __restrict__ b2b,
    float* __restrict__ out)
{
    __shared__ float Ss[16][128];
    __shared__ float Zs[16][192];
    __shared__ float Ys[16][128];
    __shared__ float sdeg[16];

    int t = threadIdx.x;
    int a0 = blockIdx.x * 16;

    for (int i = t; i < 16 * 128; i += 128)
        Ss[i >> 7][i & 127] = g_agg[(size_t)a0 * HH + i];
    if (t < 16) sdeg[t] = (float)g_cnt[a0 + t];
    for (int i = t; i < 16 * 64; i += 128)
        Zs[i >> 6][i & 63] = ap_hid[(size_t)a0 * DD + i];
    __syncthreads();

    // stage 1: Zs[r][64+c] = deg[r]*b1b[c] + sum_k Ss[r][k]*W1b[k][c]
    {
        int c = t;
        float acc[16];
        float bb = b1b[c];
        #pragma unroll
        for (int r = 0; r < 16; r++) acc[r] = sdeg[r] * bb;
        for (int k = 0; k < 128; k++) {
            float wv = W1b[k * HH + c];
            #pragma unroll
            for (int r = 0; r < 16; r++) acc[r] += Ss[r][k] * wv;
        }
        #pragma unroll
        for (int r = 0; r < 16; r++) Zs[r][64 + c] = acc[r];
    }
    __syncthreads();

    // stage 2: Ys = relu(Zs @ W2a + b2a)
    {
        int c = t;
        float acc[16];
        float bb = b2a[c];
        #pragma unroll
        for (int r = 0; r < 16; r++) acc[r] = bb;
        for (int k = 0; k < 192; k++) {
            float wv = W2a[k * HH + c];
            #pragma unroll
            for (int r = 0; r < 16; r++) acc[r] += Zs[r][k] * wv;
        }
        #pragma unroll
        for (int r = 0; r < 16; r++) Ys[r][c] = fmaxf(acc[r], 0.f);
    }
    __syncthreads();

    // stage 3: out = Ys @ W2b + b2b
    {
        int c = t & 63, rg = t >> 6;
        float acc[8];
        float bb = b2b[c];
        #pragma unroll
        for (int j = 0; j < 8; j++) acc[j] = bb;
        for (int k = 0; k < 128; k++) {
            float wv = W2b[k * DD + c];
            #pragma unroll
            for (int j = 0; j < 8; j++) acc[j] += Ys[rg * 8 + j][k] * wv;
        }
        #pragma unroll
        for (int j = 0; j < 8; j++)
            out[(size_t)(a0 + rg * 8 + j) * DD + c] = acc[j];
    }
}

// ---------------- launch ----------------------------------------------------
extern "C" void kernel_launch(void* const* d_in, const int* in_sizes, int n_in,
                              void* d_out, int out_size) {
    const float* ue_hid   = (const float*)d_in[0];
    const float* ap_hid   = (const float*)d_in[1];
    const float* edge_hid = (const float*)d_in[2];
    const int*   src      = (const int*)d_in[3];
    const int*   dst      = (const int*)d_in[4];
    const float* W1a      = (const float*)d_in[5];
    const float* b1a      = (const float*)d_in[6];
    const float* W1b      = (const float*)d_in[7];
    const float* b1b      = (const float*)d_in[8];
    const float* W2a      = (const float*)d_in[9];
    const float* b2a      = (const float*)d_in[10];
    const float* W2b      = (const float*)d_in[11];
    const float* b2b      = (const float*)d_in[12];
    float* out = (float*)d_out;

    cudaFuncSetAttribute(k_main, cudaFuncAttributeMaxDynamicSharedMemorySize, SMEM_MAIN);

    k_zero<<<5000, 256>>>();                                   // launch 0
    k_hist<<<(N_E + 255) / 256, 256>>>(dst);                   // launch 1
    k_scan_prep<<<9, 1024>>>(W1a);                             // launch 2 (scan + weight prep)
    k_scatter<<<(N_E + 255) / 256, 256>>>(src, dst);           // launch 3
    k_ueproj<<<(N_UE + 63) / 64, 256>>>(ue_hid, W1a, b1a);     // launch 4
    k_main<<<PGRID, 256, SMEM_MAIN>>>(edge_hid);               // launch 5  (ncu -s 5 target)
    k_final<<<N_AP / 16, 128>>>(ap_hid, W1b, b1b, W2a, b2a, W2b, b2b, out);  // launch 6
}

// round 7
// speedup vs baseline: 1.3846x; 1.3846x over previous
#include <cuda_runtime.h>
#include <cuda_fp16.h>
#include <cstdint>

#define N_UE 100000
#define N_AP 10000
#define N_E  1600000
#define DD   64
#define HH   128
#define TILES (N_E / 128)          // 12500

// ---------------- scratch (device globals; no allocation allowed) ----------
__device__ float g_ueproj[(size_t)N_UE * HH];      // ue_hid @ W1a[64:] + b1a
__device__ float g_agg[(size_t)N_AP * HH];         // segment_sum(relu(...))
__device__ int   g_cnt[N_AP];
__device__ int   g_cursor[N_AP];
__device__ int4  g_meta[N_E];                      // (edge_idx, src, dst, 0) sorted by dst
__device__ unsigned g_wt_hi2[4096];                // W1a[:64]^T as half2 pairs [n][k2]
__device__ unsigned g_wt_lo2[4096];                // f16 residual plane

// ---------------- small setup kernels --------------------------------------
__global__ void k_zero() {
    int i = blockIdx.x * 256 + threadIdx.x;
    if (i < N_AP * HH) g_agg[i] = 0.f;
    if (i < N_AP) g_cnt[i] = 0;
}

__global__ void k_hist(const int* __restrict__ dst) {
    int i = blockIdx.x * 256 + threadIdx.x;
    if (i < N_E) atomicAdd(&g_cnt[dst[i]], 1);
}

// block 0: exclusive prefix over 10000 bins -> g_cursor.
// blocks 1..4: prepare f16 hi/lo weight planes (transposed, half2-packed).
__global__ void k_scan_prep(const float* __restrict__ W1a) {
    if (blockIdx.x == 0) {
        __shared__ int buf[1024];
        int t = threadIdx.x;
        int local[16];
        int s = 0;
        if (t < 625) {
            #pragma unroll
            for (int j = 0; j < 16; j++) { local[j] = s; s += g_cnt[t * 16 + j]; }
        }
        buf[t] = s;
        __syncthreads();
        int own = s;
        for (int off = 1; off < 1024; off <<= 1) {
            int v = 0;
            if (t >= off) v = buf[t - off];
            __syncthreads();
            buf[t] += v;
            __syncthreads();
        }
        int excl = buf[t] - own;
        if (t < 625) {
            #pragma unroll
            for (int j = 0; j < 16; j++) g_cursor[t * 16 + j] = excl + local[j];
        }
    } else {
        int j = (blockIdx.x - 1) * 1024 + threadIdx.x;   // 4096 half2 pairs
        if (j < 4096) {
            int n = j >> 5, k2 = j & 31;                 // pair covers k = 2*k2, 2*k2+1
            float v0 = W1a[(k2 * 2) * HH + n];           // Wt[n][k] = W1a[k][n], k<64
            float v1 = W1a[(k2 * 2 + 1) * HH + n];
            __half2 h = __floats2half2_rn(v0, v1);
            float2 f = __half22float2(h);
            __half2 lo = __floats2half2_rn(v0 - f.x, v1 - f.y);
            g_wt_hi2[j] = *(unsigned*)&h;
            g_wt_lo2[j] = *(unsigned*)&lo;
        }
    }
}

__global__ void k_scatter(const int* __restrict__ src, const int* __restrict__ dst) {
    int i = blockIdx.x * 256 + threadIdx.x;
    if (i < N_E) {
        int d = dst[i];
        int p = atomicAdd(&g_cursor[d], 1);
        g_meta[p] = make_int4(i, src[i], d, 0);
    }
}

// ---------------- ue projection: g_ueproj = ue_hid @ W1a[64:128] + b1a -----
__global__ void __launch_bounds__(256) k_ueproj(
    const float* __restrict__ ue_hid, const float* __restrict__ W1a,
    const float* __restrict__ b1a)
{
    __shared__ float us[64][64];
    int t = threadIdx.x;
    int rbase = blockIdx.x * 64;

    for (int f = t; f < 1024; f += 256) {
        int row = f >> 4, c4 = f & 15;
        float4 v = make_float4(0.f, 0.f, 0.f, 0.f);
        if (rbase + row < N_UE)
            v = *(const float4*)(ue_hid + (size_t)(rbase + row) * DD + c4 * 4);
        *(float4*)(&us[row][c4 * 4]) = v;
    }

    int c = t & 127;
    int rh = t >> 7;
    float wc[64];
    #pragma unroll 8
    for (int k = 0; k < 64; k++) wc[k] = W1a[(64 + k) * HH + c];
    float bb = b1a[c];
    __syncthreads();

    for (int i = 0; i < 32; i++) {
        int r = rh * 32 + i;
        int gr = rbase + r;
        if (gr >= N_UE) break;          // uniform per warp
        float acc = bb;
        #pragma unroll
        for (int k4 = 0; k4 < 16; k4++) {
            float4 u4 = *(const float4*)(&us[r][k4 * 4]);
            acc += u4.x * wc[k4 * 4 + 0];
            acc += u4.y * wc[k4 * 4 + 1];
            acc += u4.z * wc[k4 * 4 + 2];
            acc += u4.w * wc[k4 * 4 + 3];
        }
        g_ueproj[(size_t)gr * HH + c] = acc;
    }
}

// ---------------- main edge kernel: f16 2-plane mma + segmented reduce -----
__device__ __forceinline__ void mma_f16(float c[4],
    unsigned a0, unsigned a1, unsigned a2, unsigned a3,
    unsigned b0, unsigned b1)
{
    asm volatile(
        "mma.sync.aligned.m16n8k16.row.col.f32.f16.f16.f32 "
        "{%0,%1,%2,%3}, {%4,%5,%6,%7}, {%8,%9}, {%0,%1,%2,%3};\n"
        : "+f"(c[0]), "+f"(c[1]), "+f"(c[2]), "+f"(c[3])
        : "r"(a0), "r"(a1), "r"(a2), "r"(a3), "r"(b0), "r"(b1));
}

#define ASTR 72                          // padded smem stride (f16 elems)
#define HSTR 66                          // Hs stride (floats), per 64-col pass
#define SMEM_MAIN (3 * 128 * ASTR * 2)   // 55296 B: A(18432) Bh(18432) Bl(18432)

__global__ void __launch_bounds__(256, 2) k_main(const float* __restrict__ edge_hid)
{
    extern __shared__ char sraw[];
    __half* Ah = (__half*)sraw;                        // [128][72] single f16 plane
    __half* Bh = Ah + 128 * ASTR;                      // Wt hi [n=128][k=64]
    __half* Bl = Bh + 128 * ASTR;                      // Wt lo
    float* Hs = (float*)sraw;                          // [128][66], reused after mma
    __shared__ int s_src[128];
    __shared__ int s_dst[128];

    int t = threadIdx.x;
    int base = blockIdx.x * 128;

    // meta -> smem
    if (t < 128) {
        int4 m = g_meta[base + t];
        s_src[t] = m.y;
        s_dst[t] = m.z;
    }

    // stage weights (half2-vectorized copy of both planes)
    for (int j = t; j < 4096; j += 256) {
        int n = j >> 5, k2 = j & 31;
        *(unsigned*)(Bh + n * ASTR + k2 * 2) = g_wt_hi2[j];
        *(unsigned*)(Bl + n * ASTR + k2 * 2) = g_wt_lo2[j];
    }

    // gather + convert 128 edge rows to f16 (row = t>>1, half = t&1)
    {
        int row = t >> 1, half = t & 1;
        int e = g_meta[base + row].x;
        const float4* src4 = (const float4*)(edge_hid + (size_t)e * DD + half * 32);
        int sb = row * ASTR + half * 32;
        #pragma unroll
        for (int q = 0; q < 8; q++) {
            float4 v = src4[q];
            __half2 h01 = __floats2half2_rn(v.x, v.y);
            __half2 h23 = __floats2half2_rn(v.z, v.w);
            *(__half2*)(Ah + sb + q * 4)     = h01;
            *(__half2*)(Ah + sb + q * 4 + 2) = h23;
        }
    }
    __syncthreads();

    int w = t >> 5, l = t & 31;
    int g = l >> 2, q4 = l & 3;
    int ar = w * 16 + g;                 // warp w owns rows [16w,16w+16)

    float C[16][4];
    #pragma unroll
    for (int nf = 0; nf < 16; nf++) { C[nf][0] = C[nf][1] = C[nf][2] = C[nf][3] = 0.f; }

    #pragma unroll
    for (int kt = 0; kt < 4; kt++) {
        int k0 = kt * 16 + q4 * 2;
        unsigned a0 = *(const unsigned*)(Ah + ar * ASTR + k0);
        unsigned a1 = *(const unsigned*)(Ah + (ar + 8) * ASTR + k0);
        unsigned a2 = *(const unsigned*)(Ah + ar * ASTR + k0 + 8);
        unsigned a3 = *(const unsigned*)(Ah + (ar + 8) * ASTR + k0 + 8);
        #pragma unroll
        for (int nf = 0; nf < 16; nf++) {
            int n = nf * 8 + g;
            unsigned bh0 = *(const unsigned*)(Bh + n * ASTR + k0);
            unsigned bh1 = *(const unsigned*)(Bh + n * ASTR + k0 + 8);
            unsigned bl0 = *(const unsigned*)(Bl + n * ASTR + k0);
            unsigned bl1 = *(const unsigned*)(Bl + n * ASTR + k0 + 8);
            mma_f16(C[nf], a0, a1, a2, a3, bh0, bh1);   // A * B_hi
            mma_f16(C[nf], a0, a1, a2, a3, bl0, bl1);   // A * B_lo
        }
    }
    __syncthreads();   // all warps done reading A/B -> Hs may overwrite

    int s0 = s_src[ar], s1 = s_src[ar + 8];
    const float* up0 = g_ueproj + (size_t)s0 * HH;
    const float* up1 = g_ueproj + (size_t)s1 * HH;

    #pragma unroll
    for (int pass = 0; pass < 2; pass++) {
        // epilogue: + ue_proj[src] gather, relu, stage 64 columns to Hs
        #pragma unroll
        for (int nfl = 0; nfl < 8; nfl++) {
            int nf = pass * 8 + nfl;
            int c0 = nf * 8 + q4 * 2;       // global column
            int lc = c0 - pass * 64;        // local column in Hs
            float2 u0 = *(const float2*)(up0 + c0);
            float2 u1 = *(const float2*)(up1 + c0);
            float2 v0, v1;
            v0.x = fmaxf(C[nf][0] + u0.x, 0.f);
            v0.y = fmaxf(C[nf][1] + u0.y, 0.f);
            v1.x = fmaxf(C[nf][2] + u1.x, 0.f);
            v1.y = fmaxf(C[nf][3] + u1.y, 0.f);
            *(float2*)(Hs + ar * HSTR + lc) = v0;
            *(float2*)(Hs + (ar + 8) * HSTR + lc) = v1;
        }
        __syncthreads();

        // segmented reduce over sorted dst: 4 row-quarters x 64 cols
        {
            int cl = t & 63, qr = t >> 6;
            int r0 = qr * 32;
            float acc = 0.f;
            int prev = s_dst[r0];
            #pragma unroll 4
            for (int i = 0; i < 32; i++) {
                int r = r0 + i;
                int d = s_dst[r];
                if (d != prev) {
                    atomicAdd(&g_agg[(size_t)prev * HH + pass * 64 + cl], acc);
                    acc = 0.f; prev = d;
                }
                acc += Hs[r * HSTR + cl];
            }
            atomicAdd(&g_agg[(size_t)prev * HH + pass * 64 + cl], acc);
        }
        if (pass == 0) __syncthreads();   // Hs readers done before pass-2 writes
    }
}

// ---------------- final AP MLP: agg@W1b + deg*b1b, concat, mlp2 ------------
__global__ void __launch_bounds__(128) k_final(
    const float* __restrict__ ap_hid,
    const float* __restrict__ W1b, const float* __restrict__ b1b,
    const float* __restrict__ W2a, const float* __restrict__ b2a,
    const float* __restrict__ W2b, const float* __restrict__ b2b,
    float* __restrict__ out)
{
    __shared__ float Ss[16][128];
    __shared__ float Zs[16][192];
    __shared__ float Ys[16][128];
    __shared__ float sdeg[16];

    int t = threadIdx.x;
    int a0 = blockIdx.x * 16;

    for (int i = t; i < 16 * 128; i += 128)
        Ss[i >> 7][i & 127] = g_agg[(size_t)a0 * HH + i];
    if (t < 16) sdeg[t] = (float)g_cnt[a0 + t];
    for (int i = t; i < 16 * 64; i += 128)
        Zs[i >> 6][i & 63] = ap_hid[(size_t)a0 * DD + i];
    __syncthreads();

    // stage 1: Zs[r][64+c] = deg[r]*b1b[c] + sum_k Ss[r][k]*W1b[k][c]
    {
        int c = t;
        float acc[16];
        float bb = b1b[c];
        #pragma unroll
        for (int r = 0; r < 16; r++) acc[r] = sdeg[r] * bb;
        for (int k = 0; k < 128; k++) {
            float wv = W1b[k * HH + c];
            #pragma unroll
            for (int r = 0; r < 16; r++) acc[r] += Ss[r][k] * wv;
        }
        #pragma unroll
        for (int r = 0; r < 16; r++) Zs[r][64 + c] = acc[r];
    }
    __syncthreads();

    // stage 2: Ys = relu(Zs @ W2a + b2a)
    {
        int c = t;
        float acc[16];
        float bb = b2a[c];
        #pragma unroll
        for (int r = 0; r < 16; r++) acc[r] = bb;
        for (int k = 0; k < 192; k++) {
            float wv = W2a[k * HH + c];
            #pragma unroll
            for (int r = 0; r < 16; r++) acc[r] += Zs[r][k] * wv;
        }
        #pragma unroll
        for (int r = 0; r < 16; r++) Ys[r][c] = fmaxf(acc[r], 0.f);
    }
    __syncthreads();

    // stage 3: out = Ys @ W2b + b2b
    {
        int c = t & 63, rg = t >> 6;
        float acc[8];
        float bb = b2b[c];
        #pragma unroll
        for (int j = 0; j < 8; j++) acc[j] = bb;
        for (int k = 0; k < 128; k++) {
            float wv = W2b[k * DD + c];
            #pragma unroll
            for (int j = 0; j < 8; j++) acc[j] += Ys[rg * 8 + j][k] * wv;
        }
        #pragma unroll
        for (int j = 0; j < 8; j++)
            out[(size_t)(a0 + rg * 8 + j) * DD + c] = acc[j];
    }
}

// ---------------- launch ----------------------------------------------------
extern "C" void kernel_launch(void* const* d_in, const int* in_sizes, int n_in,
                              void* d_out, int out_size) {
    const float* ue_hid   = (const float*)d_in[0];
    const float* ap_hid   = (const float*)d_in[1];
    const float* edge_hid = (const float*)d_in[2];
    const int*   src      = (const int*)d_in[3];
    const int*   dst      = (const int*)d_in[4];
    const float* W1a      = (const float*)d_in[5];
    const float* b1a      = (const float*)d_in[6];
    const float* W1b      = (const float*)d_in[7];
    const float* b1b      = (const float*)d_in[8];
    const float* W2a      = (const float*)d_in[9];
    const float* b2a      = (const float*)d_in[10];
    const float* W2b      = (const float*)d_in[11];
    const float* b2b      = (const float*)d_in[12];
    float* out = (float*)d_out;

    cudaFuncSetAttribute(k_main, cudaFuncAttributeMaxDynamicSharedMemorySize, SMEM_MAIN);

    k_zero<<<5000, 256>>>();
    k_hist<<<(N_E + 255) / 256, 256>>>(dst);
    k_scan_prep<<<5, 1024>>>(W1a);
    k_scatter<<<(N_E + 255) / 256, 256>>>(src, dst);
    k_ueproj<<<(N_UE + 63) / 64, 256>>>(ue_hid, W1a, b1a);
    k_main<<<TILES, 256, SMEM_MAIN>>>(edge_hid);
    k_final<<<N_AP / 16, 128>>>(ap_hid, W1b, b1b, W2a, b2a, W2b, b2b, out);
}

// round 10
// speedup vs baseline: 1.4510x; 1.0480x over previous
#include <cuda_runtime.h>
#include <cuda_fp16.h>
#include <cstdint>

#define N_UE 100000
#define N_AP 10000
#define N_E  1600000
#define DD   64
#define HH   128
#define TILES (N_E / 128)          // 12500
#define SCAT_BLOCKS ((N_E + 255) / 256)     // 6250
#define UEP_BLOCKS  ((N_UE + 63) / 64)      // 1563

// ---------------- scratch (device globals; no allocation allowed) ----------
// Invariant: g_cnt == 0 and g_agg == 0 at every kernel_launch entry.
// (zero-initialized at module load; restored by k_final's tail each call.)
__device__ __half g_ueproj[(size_t)N_UE * HH];   // ue_hid @ W1a[64:] + b1a (fp16)
__device__ float  g_agg[(size_t)N_AP * HH];      // segment_sum(relu(...))
__device__ int    g_cnt[N_AP];
__device__ int    g_cursor[N_AP];
__device__ int4   g_meta[N_E];                   // (edge_idx, src, dst, 0) sorted by dst
__device__ unsigned g_wt_hi2[4096];              // W1a[:64]^T as half2 pairs [n][k2]
__device__ unsigned g_wt_lo2[4096];              // f16 residual plane

// ---------------- launch 0: histogram --------------------------------------
__global__ void k_hist(const int* __restrict__ dst) {
    int i = blockIdx.x * 256 + threadIdx.x;
    if (i < N_E) atomicAdd(&g_cnt[dst[i]], 1);
}

// ---------------- launch 1: scan + weight prep ------------------------------
// block 0: exclusive prefix over 10000 bins -> g_cursor.
// blocks 1..4: prepare f16 hi/lo weight planes (transposed, half2-packed).
__global__ void k_scan_prep(const float* __restrict__ W1a) {
    if (blockIdx.x == 0) {
        __shared__ int buf[1024];
        int t = threadIdx.x;
        int local[16];
        int s = 0;
        if (t < 625) {
            #pragma unroll
            for (int j = 0; j < 16; j++) { local[j] = s; s += g_cnt[t * 16 + j]; }
        }
        buf[t] = s;
        __syncthreads();
        int own = s;
        for (int off = 1; off < 1024; off <<= 1) {
            int v = 0;
            if (t >= off) v = buf[t - off];
            __syncthreads();
            buf[t] += v;
            __syncthreads();
        }
        int excl = buf[t] - own;
        if (t < 625) {
            #pragma unroll
            for (int j = 0; j < 16; j++) g_cursor[t * 16 + j] = excl + local[j];
        }
    } else {
        int j = (blockIdx.x - 1) * 1024 + threadIdx.x;   // 4096 half2 pairs
        if (j < 4096) {
            int n = j >> 5, k2 = j & 31;                 // pair covers k = 2*k2, 2*k2+1
            float v0 = W1a[(k2 * 2) * HH + n];           // Wt[n][k] = W1a[k][n], k<64
            float v1 = W1a[(k2 * 2 + 1) * HH + n];
            __half2 h = __floats2half2_rn(v0, v1);
            float2 f = __half22float2(h);
            __half2 lo = __floats2half2_rn(v0 - f.x, v1 - f.y);
            g_wt_hi2[j] = *(unsigned*)&h;
            g_wt_lo2[j] = *(unsigned*)&lo;
        }
    }
}

// ---------------- launch 2: fused scatter + ue projection -------------------
// blocks [0, SCAT_BLOCKS): counting-sort scatter of edge meta.
// blocks [SCAT_BLOCKS, +UEP_BLOCKS): g_ueproj = f16(ue_hid @ W1a[64:] + b1a).
__global__ void __launch_bounds__(256) k_scatter_ueproj(
    const int* __restrict__ src, const int* __restrict__ dst,
    const float* __restrict__ ue_hid, const float* __restrict__ W1a,
    const float* __restrict__ b1a)
{
    __shared__ float us[64][64];
    int t = threadIdx.x;

    if (blockIdx.x < SCAT_BLOCKS) {
        int i = blockIdx.x * 256 + t;
        if (i < N_E) {
            int d = dst[i];
            int p = atomicAdd(&g_cursor[d], 1);
            g_meta[p] = make_int4(i, src[i], d, 0);
        }
        return;
    }

    int rbase = (blockIdx.x - SCAT_BLOCKS) * 64;

    for (int f = t; f < 1024; f += 256) {
        int row = f >> 4, c4 = f & 15;
        float4 v = make_float4(0.f, 0.f, 0.f, 0.f);
        if (rbase + row < N_UE)
            v = *(const float4*)(ue_hid + (size_t)(rbase + row) * DD + c4 * 4);
        *(float4*)(&us[row][c4 * 4]) = v;
    }

    int c = t & 127;
    int rh = t >> 7;
    float wc[64];
    #pragma unroll 8
    for (int k = 0; k < 64; k++) wc[k] = W1a[(64 + k) * HH + c];
    float bb = b1a[c];
    __syncthreads();

    for (int i = 0; i < 32; i++) {
        int r = rh * 32 + i;
        int gr = rbase + r;
        if (gr >= N_UE) break;          // uniform per warp
        float acc = bb;
        #pragma unroll
        for (int k4 = 0; k4 < 16; k4++) {
            float4 u4 = *(const float4*)(&us[r][k4 * 4]);
            acc += u4.x * wc[k4 * 4 + 0];
            acc += u4.y * wc[k4 * 4 + 1];
            acc += u4.z * wc[k4 * 4 + 2];
            acc += u4.w * wc[k4 * 4 + 3];
        }
        g_ueproj[(size_t)gr * HH + c] = __float2half(acc);
    }
}

// ---------------- launch 3: main edge kernel (PROFILED INDEX) ---------------
__device__ __forceinline__ void mma_f16(float c[4],
    unsigned a0, unsigned a1, unsigned a2, unsigned a3,
    unsigned b0, unsigned b1)
{
    asm volatile(
        "mma.sync.aligned.m16n8k16.row.col.f32.f16.f16.f32 "
        "{%0,%1,%2,%3}, {%4,%5,%6,%7}, {%8,%9}, {%0,%1,%2,%3};\n"
        : "+f"(c[0]), "+f"(c[1]), "+f"(c[2]), "+f"(c[3])
        : "r"(a0), "r"(a1), "r"(a2), "r"(a3), "r"(b0), "r"(b1));
}

#define ASTR 72                          // padded smem stride (f16 elems)
#define HSTR 66                          // Hs stride (floats), per 64-col pass
#define SMEM_MAIN (3 * 128 * ASTR * 2)   // 55296 B: A(18432) Bh(18432) Bl(18432)

__global__ void __launch_bounds__(256, 2) k_main(const float* __restrict__ edge_hid)
{
    extern __shared__ char sraw[];
    __half* Ah = (__half*)sraw;                        // [128][72] single f16 plane
    __half* Bh = Ah + 128 * ASTR;                      // Wt hi [n=128][k=64]
    __half* Bl = Bh + 128 * ASTR;                      // Wt lo
    float* Hs = (float*)sraw;                          // [128][66], reused after mma
    __shared__ int s_src[128];
    __shared__ int s_dst[128];

    int t = threadIdx.x;
    int base = blockIdx.x * 128;

    // meta -> smem
    if (t < 128) {
        int4 m = g_meta[base + t];
        s_src[t] = m.y;
        s_dst[t] = m.z;
    }

    // stage weights (half2-vectorized copy of both planes)
    for (int j = t; j < 4096; j += 256) {
        int n = j >> 5, k2 = j & 31;
        *(unsigned*)(Bh + n * ASTR + k2 * 2) = g_wt_hi2[j];
        *(unsigned*)(Bl + n * ASTR + k2 * 2) = g_wt_lo2[j];
    }

    // gather + convert 128 edge rows to f16 (row = t>>1, half = t&1)
    {
        int row = t >> 1, half = t & 1;
        int e = g_meta[base + row].x;
        const float4* src4 = (const float4*)(edge_hid + (size_t)e * DD + half * 32);
        int sb = row * ASTR + half * 32;
        #pragma unroll
        for (int q = 0; q < 8; q++) {
            float4 v = src4[q];
            __half2 h01 = __floats2half2_rn(v.x, v.y);
            __half2 h23 = __floats2half2_rn(v.z, v.w);
            *(__half2*)(Ah + sb + q * 4)     = h01;
            *(__half2*)(Ah + sb + q * 4 + 2) = h23;
        }
    }
    __syncthreads();

    int w = t >> 5, l = t & 31;
    int g = l >> 2, q4 = l & 3;
    int ar = w * 16 + g;                 // warp w owns rows [16w,16w+16)

    float C[16][4];
    #pragma unroll
    for (int nf = 0; nf < 16; nf++) { C[nf][0] = C[nf][1] = C[nf][2] = C[nf][3] = 0.f; }

    #pragma unroll
    for (int kt = 0; kt < 4; kt++) {
        int k0 = kt * 16 + q4 * 2;
        unsigned a0 = *(const unsigned*)(Ah + ar * ASTR + k0);
        unsigned a1 = *(const unsigned*)(Ah + (ar + 8) * ASTR + k0);
        unsigned a2 = *(const unsigned*)(Ah + ar * ASTR + k0 + 8);
        unsigned a3 = *(const unsigned*)(Ah + (ar + 8) * ASTR + k0 + 8);
        #pragma unroll
        for (int nf = 0; nf < 16; nf++) {
            int n = nf * 8 + g;
            unsigned bh0 = *(const unsigned*)(Bh + n * ASTR + k0);
            unsigned bh1 = *(const unsigned*)(Bh + n * ASTR + k0 + 8);
            unsigned bl0 = *(const unsigned*)(Bl + n * ASTR + k0);
            unsigned bl1 = *(const unsigned*)(Bl + n * ASTR + k0 + 8);
            mma_f16(C[nf], a0, a1, a2, a3, bh0, bh1);   // A * B_hi
            mma_f16(C[nf], a0, a1, a2, a3, bl0, bl1);   // A * B_lo
        }
    }
    __syncthreads();   // all warps done reading A/B -> Hs may overwrite

    int s0 = s_src[ar], s1 = s_src[ar + 8];
    const __half* up0 = g_ueproj + (size_t)s0 * HH;
    const __half* up1 = g_ueproj + (size_t)s1 * HH;

    #pragma unroll
    for (int pass = 0; pass < 2; pass++) {
        // epilogue: + ue_proj[src] (f16 gather), relu, stage 64 columns to Hs
        #pragma unroll
        for (int nfl = 0; nfl < 8; nfl++) {
            int nf = pass * 8 + nfl;
            int c0 = nf * 8 + q4 * 2;       // global column
            int lc = c0 - pass * 64;        // local column in Hs
            float2 u0 = __half22float2(*(const __half2*)(up0 + c0));
            float2 u1 = __half22float2(*(const __half2*)(up1 + c0));
            float2 v0, v1;
            v0.x = fmaxf(C[nf][0] + u0.x, 0.f);
            v0.y = fmaxf(C[nf][1] + u0.y, 0.f);
            v1.x = fmaxf(C[nf][2] + u1.x, 0.f);
            v1.y = fmaxf(C[nf][3] + u1.y, 0.f);
            *(float2*)(Hs + ar * HSTR + lc) = v0;
            *(float2*)(Hs + (ar + 8) * HSTR + lc) = v1;
        }
        __syncthreads();

        // segmented reduce over sorted dst: 4 row-quarters x 64 cols
        {
            int cl = t & 63, qr = t >> 6;
            int r0 = qr * 32;
            float acc = 0.f;
            int prev = s_dst[r0];
            #pragma unroll 4
            for (int i = 0; i < 32; i++) {
                int r = r0 + i;
                int d = s_dst[r];
                if (d != prev) {
                    atomicAdd(&g_agg[(size_t)prev * HH + pass * 64 + cl], acc);
                    acc = 0.f; prev = d;
                }
                acc += Hs[r * HSTR + cl];
            }
            atomicAdd(&g_agg[(size_t)prev * HH + pass * 64 + cl], acc);
        }
        if (pass == 0) __syncthreads();   // Hs readers done before pass-2 writes
    }
}

// ---------------- launch 4: final AP MLP + scratch cleanup ------------------
__global__ void __launch_bounds__(128) k_final(
    const float* __restrict__ ap_hid,
    const float* __restrict__ W1b, const float* __restrict__ b1b,
    const float* __restrict__ W2a, const float* __restrict__ b2a,
    const float* __restrict__ W2b, const float* __restrict__ b2b,
    float* __restrict__ out)
{
    __shared__ float Ss[16][128];
    __shared__ float Zs[16][192];
    __shared__ float Ys[16][128];
    __shared__ float sdeg[16];

    int t = threadIdx.x;
    int a0 = blockIdx.x * 16;

    for (int i = t; i < 16 * 128; i += 128)
        Ss[i >> 7][i & 127] = g_agg[(size_t)a0 * HH + i];
    if (t < 16) sdeg[t] = (float)g_cnt[a0 + t];
    for (int i = t; i < 16 * 64; i += 128)
        Zs[i >> 6][i & 63] = ap_hid[(size_t)a0 * DD + i];
    __syncthreads();

    // restore scratch invariant for the next kernel_launch call (this block's slice)
    for (int i = t; i < 16 * 128; i += 128)
        g_agg[(size_t)a0 * HH + i] = 0.f;
    if (t < 16) g_cnt[a0 + t] = 0;

    // stage 1: Zs[r][64+c] = deg[r]*b1b[c] + sum_k Ss[r][k]*W1b[k][c]
    {
        int c = t;
        float acc[16];
        float bb = b1b[c];
        #pragma unroll
        for (int r = 0; r < 16; r++) acc[r] = sdeg[r] * bb;
        for (int k = 0; k < 128; k++) {
            float wv = W1b[k * HH + c];
            #pragma unroll
            for (int r = 0; r < 16; r++) acc[r] += Ss[r][k] * wv;
        }
        #pragma unroll
        for (int r = 0; r < 16; r++) Zs[r][64 + c] = acc[r];
    }
    __syncthreads();

    // stage 2: Ys = relu(Zs @ W2a + b2a)
    {
        int c = t;
        float acc[16];
        float bb = b2a[c];
        #pragma unroll
        for (int r = 0; r < 16; r++) acc[r] = bb;
        for (int k = 0; k < 192; k++) {
            float wv = W2a[k * HH + c];
            #pragma unroll
            for (int r = 0; r < 16; r++) acc[r] += Zs[r][k] * wv;
        }
        #pragma unroll
        for (int r = 0; r < 16; r++) Ys[r][c] = fmaxf(acc[r], 0.f);
    }
    __syncthreads();

    // stage 3: out = Ys @ W2b + b2b
    {
        int c = t & 63, rg = t >> 6;
        float acc[8];
        float bb = b2b[c];
        #pragma unroll
        for (int j = 0; j < 8; j++) acc[j] = bb;
        for (int k = 0; k < 128; k++) {
            float wv = W2b[k * DD + c];
            #pragma unroll
            for (int j = 0; j < 8; j++) acc[j] += Ys[rg * 8 + j][k] * wv;
        }
        #pragma unroll
        for (int j = 0; j < 8; j++)
            out[(size_t)(a0 + rg * 8 + j) * DD + c] = acc[j];
    }
}

// ---------------- launch ----------------------------------------------------
extern "C" void kernel_launch(void* const* d_in, const int* in_sizes, int n_in,
                              void* d_out, int out_size) {
    const float* ue_hid   = (const float*)d_in[0];
    const float* ap_hid   = (const float*)d_in[1];
    const float* edge_hid = (const float*)d_in[2];
    const int*   src      = (const int*)d_in[3];
    const int*   dst      = (const int*)d_in[4];
    const float* W1a      = (const float*)d_in[5];
    const float* b1a      = (const float*)d_in[6];
    const float* W1b      = (const float*)d_in[7];
    const float* b1b      = (const float*)d_in[8];
    const float* W2a      = (const float*)d_in[9];
    const float* b2a      = (const float*)d_in[10];
    const float* W2b      = (const float*)d_in[11];
    const float* b2b      = (const float*)d_in[12];
    float* out = (float*)d_out;

    cudaFuncSetAttribute(k_main, cudaFuncAttributeMaxDynamicSharedMemorySize, SMEM_MAIN);

    k_hist<<<SCAT_BLOCKS, 256>>>(dst);                                     // 0
    k_scan_prep<<<5, 1024>>>(W1a);                                         // 1
    k_scatter_ueproj<<<SCAT_BLOCKS + UEP_BLOCKS, 256>>>(src, dst,
                                                        ue_hid, W1a, b1a); // 2
    k_main<<<TILES, 256, SMEM_MAIN>>>(edge_hid);                           // 3 (profiled)
    k_final<<<N_AP / 16, 128>>>(ap_hid, W1b, b1b, W2a, b2a, W2b, b2b, out);// 4
}

// round 11
// speedup vs baseline: 1.6742x; 1.1538x over previous
#include <cuda_runtime.h>
#include <cuda_fp16.h>
#include <cstdint>

#define N_UE 100000
#define N_AP 10000
#define N_E  1600000
#define DD   64
#define HH   128
#define TILES (N_E / 128)          // 12500
#define SCAT_BLOCKS ((N_E + 255) / 256)     // 6250
#define UEP_BLOCKS  ((N_UE + 63) / 64)      // 1563

// ---------------- scratch (device globals; no allocation allowed) ----------
// Invariant: g_cnt == 0 and g_agg == 0 at every kernel_launch entry.
__device__ __half g_ueproj[(size_t)N_UE * HH];   // ue_hid @ W1a[64:] + b1a (fp16)
__device__ float  g_agg[(size_t)N_AP * HH];      // segment_sum(relu(...))
__device__ int    g_cnt[N_AP];
__device__ int    g_cursor[N_AP];
__device__ int4   g_meta[N_E];                   // (edge_idx, src, dst, 0) sorted by dst
__device__ unsigned g_wt_hi2[4096];              // W1a[:64]^T as half2 pairs [n][k2]
__device__ unsigned g_wt_lo2[4096];              // f16 residual plane

__device__ __forceinline__ uint32_t smem_u32(const void* p) {
    uint32_t a;
    asm("{ .reg .u64 t; cvta.to.shared.u64 t, %1; cvt.u32.u64 %0, t; }" : "=r"(a) : "l"(p));
    return a;
}

// ---------------- launch 0: histogram --------------------------------------
__global__ void k_hist(const int* __restrict__ dst) {
    int i = blockIdx.x * 256 + threadIdx.x;
    if (i < N_E) atomicAdd(&g_cnt[dst[i]], 1);
}

// ---------------- launch 1: scan + weight prep ------------------------------
__global__ void k_scan_prep(const float* __restrict__ W1a) {
    if (blockIdx.x == 0) {
        __shared__ int buf[1024];
        int t = threadIdx.x;
        int local[16];
        int s = 0;
        if (t < 625) {
            #pragma unroll
            for (int j = 0; j < 16; j++) { local[j] = s; s += g_cnt[t * 16 + j]; }
        }
        buf[t] = s;
        __syncthreads();
        int own = s;
        for (int off = 1; off < 1024; off <<= 1) {
            int v = 0;
            if (t >= off) v = buf[t - off];
            __syncthreads();
            buf[t] += v;
            __syncthreads();
        }
        int excl = buf[t] - own;
        if (t < 625) {
            #pragma unroll
            for (int j = 0; j < 16; j++) g_cursor[t * 16 + j] = excl + local[j];
        }
    } else {
        int j = (blockIdx.x - 1) * 1024 + threadIdx.x;   // 4096 half2 pairs
        if (j < 4096) {
            int n = j >> 5, k2 = j & 31;                 // pair covers k = 2*k2, 2*k2+1
            float v0 = W1a[(k2 * 2) * HH + n];           // Wt[n][k] = W1a[k][n], k<64
            float v1 = W1a[(k2 * 2 + 1) * HH + n];
            __half2 h = __floats2half2_rn(v0, v1);
            float2 f = __half22float2(h);
            __half2 lo = __floats2half2_rn(v0 - f.x, v1 - f.y);
            g_wt_hi2[j] = *(unsigned*)&h;
            g_wt_lo2[j] = *(unsigned*)&lo;
        }
    }
}

// ---------------- launch 2: fused scatter + ue projection -------------------
__global__ void __launch_bounds__(256) k_scatter_ueproj(
    const int* __restrict__ src, const int* __restrict__ dst,
    const float* __restrict__ ue_hid, const float* __restrict__ W1a,
    const float* __restrict__ b1a)
{
    __shared__ float us[64][64];
    int t = threadIdx.x;

    if (blockIdx.x < SCAT_BLOCKS) {
        int i = blockIdx.x * 256 + t;
        if (i < N_E) {
            int d = dst[i];
            int p = atomicAdd(&g_cursor[d], 1);
            g_meta[p] = make_int4(i, src[i], d, 0);
        }
        return;
    }

    int rbase = (blockIdx.x - SCAT_BLOCKS) * 64;

    for (int f = t; f < 1024; f += 256) {
        int row = f >> 4, c4 = f & 15;
        float4 v = make_float4(0.f, 0.f, 0.f, 0.f);
        if (rbase + row < N_UE)
            v = *(const float4*)(ue_hid + (size_t)(rbase + row) * DD + c4 * 4);
        *(float4*)(&us[row][c4 * 4]) = v;
    }

    int c = t & 127;
    int rh = t >> 7;
    float wc[64];
    #pragma unroll 8
    for (int k = 0; k < 64; k++) wc[k] = W1a[(64 + k) * HH + c];
    float bb = b1a[c];
    __syncthreads();

    for (int i = 0; i < 32; i++) {
        int r = rh * 32 + i;
        int gr = rbase + r;
        if (gr >= N_UE) break;          // uniform per warp
        float acc = bb;
        #pragma unroll
        for (int k4 = 0; k4 < 16; k4++) {
            float4 u4 = *(const float4*)(&us[r][k4 * 4]);
            acc += u4.x * wc[k4 * 4 + 0];
            acc += u4.y * wc[k4 * 4 + 1];
            acc += u4.z * wc[k4 * 4 + 2];
            acc += u4.w * wc[k4 * 4 + 3];
        }
        g_ueproj[(size_t)gr * HH + c] = __float2half(acc);
    }
}

// ---------------- launch 3: main edge kernel (PROFILED INDEX) ---------------
__device__ __forceinline__ void mma_f16(float c[4],
    unsigned a0, unsigned a1, unsigned a2, unsigned a3,
    unsigned b0, unsigned b1)
{
    asm volatile(
        "mma.sync.aligned.m16n8k16.row.col.f32.f16.f16.f32 "
        "{%0,%1,%2,%3}, {%4,%5,%6,%7}, {%8,%9}, {%0,%1,%2,%3};\n"
        : "+f"(c[0]), "+f"(c[1]), "+f"(c[2]), "+f"(c[3])
        : "r"(a0), "r"(a1), "r"(a2), "r"(a3), "r"(b0), "r"(b1));
}

#define LDM4(r0, r1, r2, r3, addr)                                              \
    asm volatile("ldmatrix.sync.aligned.m8n8.x4.shared.b16 {%0,%1,%2,%3}, [%4];" \
                 : "=r"(r0), "=r"(r1), "=r"(r2), "=r"(r3) : "r"(addr))

#define ASTR 72                          // padded smem stride (f16 elems)
#define HSTRH 136                        // Hs stride in halves (272B -> conflict-free)
#define SMEM_MAIN (3 * 128 * ASTR * 2)   // 55296 B: A(18432) Bh(18432) Bl(18432)

__global__ void __launch_bounds__(256, 2) k_main(const float* __restrict__ edge_hid)
{
    extern __shared__ char sraw[];
    __half* Ah = (__half*)sraw;                        // [128][72] single f16 plane
    __half* Bh = Ah + 128 * ASTR;                      // Wt hi [n=128][k=64]
    __half* Bl = Bh + 128 * ASTR;                      // Wt lo
    __half2* Hs2 = (__half2*)sraw;                     // [128][68] h2, reused after mma
    __shared__ int s_src[128];
    __shared__ int s_dst[128];

    int t = threadIdx.x;
    int base = blockIdx.x * 128;

    // meta -> smem
    if (t < 128) {
        int4 m = g_meta[base + t];
        s_src[t] = m.y;
        s_dst[t] = m.z;
    }

    // stage weights (half2-vectorized copy of both planes)
    for (int j = t; j < 4096; j += 256) {
        int n = j >> 5, k2 = j & 31;
        *(unsigned*)(Bh + n * ASTR + k2 * 2) = g_wt_hi2[j];
        *(unsigned*)(Bl + n * ASTR + k2 * 2) = g_wt_lo2[j];
    }

    // gather + convert 128 edge rows to f16 (row = t>>1, half = t&1)
    {
        int row = t >> 1, half = t & 1;
        int e = g_meta[base + row].x;
        const float4* src4 = (const float4*)(edge_hid + (size_t)e * DD + half * 32);
        int sb = row * ASTR + half * 32;
        #pragma unroll
        for (int q = 0; q < 8; q++) {
            float4 v = src4[q];
            __half2 h01 = __floats2half2_rn(v.x, v.y);
            __half2 h23 = __floats2half2_rn(v.z, v.w);
            *(__half2*)(Ah + sb + q * 4)     = h01;
            *(__half2*)(Ah + sb + q * 4 + 2) = h23;
        }
    }
    __syncthreads();

    int w = t >> 5, l = t & 31;
    int g = l >> 2, q4 = l & 3;
    int ar = w * 16 + g;                 // warp w owns rows [16w,16w+16)

    // ldmatrix per-thread source addresses (matrix id m = l>>3, row r = l&7)
    int lm = l >> 3, lr = l & 7;
    // A x4: m0 rows 16w+0..7 @k0 | m1 rows +8 @k0 | m2 rows 0..7 @k0+8 | m3 +8 @k0+8
    uint32_t aA = smem_u32(Ah) + (uint32_t)(((16 * w + (lm & 1) * 8 + lr) * ASTR
                                             + (lm >> 1) * 8) * 2);
    // B x4 (per 16-n block p): m0 rows 16p+0..7 @k0 | m1 same rows @k0+8
    //                          m2 rows 16p+8..15 @k0 | m3 same @k0+8
    uint32_t bOff = (uint32_t)((((lm >> 1) * 8 + lr) * ASTR + (lm & 1) * 8) * 2);
    uint32_t aBh = smem_u32(Bh) + bOff;
    uint32_t aBl = smem_u32(Bl) + bOff;

    float C[16][4];
    #pragma unroll
    for (int nf = 0; nf < 16; nf++) { C[nf][0] = C[nf][1] = C[nf][2] = C[nf][3] = 0.f; }

    #pragma unroll
    for (int kt = 0; kt < 4; kt++) {
        unsigned a0, a1, a2, a3;
        LDM4(a0, a1, a2, a3, aA + kt * 32);
        #pragma unroll
        for (int pp = 0; pp < 4; pp++) {      // nf group [4pp, 4pp+4)
            unsigned h0, h1, h2, h3, h4, h5, h6, h7;
            unsigned l0, l1, l2, l3, l4, l5, l6, l7;
            uint32_t o0 = (2 * pp) * (16 * ASTR * 2) + kt * 32;
            uint32_t o1 = (2 * pp + 1) * (16 * ASTR * 2) + kt * 32;
            LDM4(h0, h1, h2, h3, aBh + o0);   // nf 4pp, 4pp+1 (hi)
            LDM4(h4, h5, h6, h7, aBh + o1);   // nf 4pp+2, 4pp+3 (hi)
            LDM4(l0, l1, l2, l3, aBl + o0);   // (lo)
            LDM4(l4, l5, l6, l7, aBl + o1);
            // hi plane: RAW distance 4 before the lo plane revisits each C
            mma_f16(C[4 * pp + 0], a0, a1, a2, a3, h0, h1);
            mma_f16(C[4 * pp + 1], a0, a1, a2, a3, h2, h3);
            mma_f16(C[4 * pp + 2], a0, a1, a2, a3, h4, h5);
            mma_f16(C[4 * pp + 3], a0, a1, a2, a3, h6, h7);
            mma_f16(C[4 * pp + 0], a0, a1, a2, a3, l0, l1);
            mma_f16(C[4 * pp + 1], a0, a1, a2, a3, l2, l3);
            mma_f16(C[4 * pp + 2], a0, a1, a2, a3, l4, l5);
            mma_f16(C[4 * pp + 3], a0, a1, a2, a3, l6, l7);
        }
    }
    __syncthreads();   // all warps done reading A/B -> Hs may overwrite

    // epilogue: + ue_proj[src] (f16 gather), relu, stage as f16 to Hs (1 pass)
    {
        int s0 = s_src[ar], s1 = s_src[ar + 8];
        const __half* up0 = g_ueproj + (size_t)s0 * HH;
        const __half* up1 = g_ueproj + (size_t)s1 * HH;
        #pragma unroll
        for (int nf = 0; nf < 16; nf++) {
            int c0 = nf * 8 + q4 * 2;
            float2 u0 = __half22float2(*(const __half2*)(up0 + c0));
            float2 u1 = __half22float2(*(const __half2*)(up1 + c0));
            __half2 v0 = __floats2half2_rn(fmaxf(C[nf][0] + u0.x, 0.f),
                                           fmaxf(C[nf][1] + u0.y, 0.f));
            __half2 v1 = __floats2half2_rn(fmaxf(C[nf][2] + u1.x, 0.f),
                                           fmaxf(C[nf][3] + u1.y, 0.f));
            Hs2[ar * (HSTRH / 2) + (c0 >> 1)] = v0;
            Hs2[(ar + 8) * (HSTRH / 2) + (c0 >> 1)] = v1;
        }
    }
    __syncthreads();

    // segmented reduce over sorted dst: 4 row-quarters x 64 half2-cols, 1 pass
    {
        int c2 = t & 63, qr = t >> 6;
        int r0 = qr * 32;
        float2 acc = make_float2(0.f, 0.f);
        int prev = s_dst[r0];
        #pragma unroll 4
        for (int i = 0; i < 32; i++) {
            int r = r0 + i;
            int d = s_dst[r];
            if (d != prev) {
                atomicAdd(&g_agg[(size_t)prev * HH + c2 * 2], acc.x);
                atomicAdd(&g_agg[(size_t)prev * HH + c2 * 2 + 1], acc.y);
                acc.x = 0.f; acc.y = 0.f; prev = d;
            }
            float2 hv = __half22float2(Hs2[r * (HSTRH / 2) + c2]);
            acc.x += hv.x;
            acc.y += hv.y;
        }
        atomicAdd(&g_agg[(size_t)prev * HH + c2 * 2], acc.x);
        atomicAdd(&g_agg[(size_t)prev * HH + c2 * 2 + 1], acc.y);
    }
}

// ---------------- launch 4: final AP MLP + scratch cleanup ------------------
__global__ void __launch_bounds__(128) k_final(
    const float* __restrict__ ap_hid,
    const float* __restrict__ W1b, const float* __restrict__ b1b,
    const float* __restrict__ W2a, const float* __restrict__ b2a,
    const float* __restrict__ W2b, const float* __restrict__ b2b,
    float* __restrict__ out)
{
    __shared__ float Ss[16][128];
    __shared__ float Zs[16][192];
    __shared__ float Ys[16][128];
    __shared__ float sdeg[16];

    int t = threadIdx.x;
    int a0 = blockIdx.x * 16;

    for (int i = t; i < 16 * 128; i += 128)
        Ss[i >> 7][i & 127] = g_agg[(size_t)a0 * HH + i];
    if (t < 16) sdeg[t] = (float)g_cnt[a0 + t];
    for (int i = t; i < 16 * 64; i += 128)
        Zs[i >> 6][i & 63] = ap_hid[(size_t)a0 * DD + i];
    __syncthreads();

    // restore scratch invariant for the next kernel_launch call
    for (int i = t; i < 16 * 128; i += 128)
        g_agg[(size_t)a0 * HH + i] = 0.f;
    if (t < 16) g_cnt[a0 + t] = 0;

    // stage 1: Zs[r][64+c] = deg[r]*b1b[c] + sum_k Ss[r][k]*W1b[k][c]
    {
        int c = t;
        float acc[16];
        float bb = b1b[c];
        #pragma unroll
        for (int r = 0; r < 16; r++) acc[r] = sdeg[r] * bb;
        for (int k = 0; k < 128; k++) {
            float wv = W1b[k * HH + c];
            #pragma unroll
            for (int r = 0; r < 16; r++) acc[r] += Ss[r][k] * wv;
        }
        #pragma unroll
        for (int r = 0; r < 16; r++) Zs[r][64 + c] = acc[r];
    }
    __syncthreads();

    // stage 2: Ys = relu(Zs @ W2a + b2a)
    {
        int c = t;
        float acc[16];
        float bb = b2a[c];
        #pragma unroll
        for (int r = 0; r < 16; r++) acc[r] = bb;
        for (int k = 0; k < 192; k++) {
            float wv = W2a[k * HH + c];
            #pragma unroll
            for (int r = 0; r < 16; r++) acc[r] += Zs[r][k] * wv;
        }
        #pragma unroll
        for (int r = 0; r < 16; r++) Ys[r][c] = fmaxf(acc[r], 0.f);
    }
    __syncthreads();

    // stage 3: out = Ys @ W2b + b2b
    {
        int c = t & 63, rg = t >> 6;
        float acc[8];
        float bb = b2b[c];
        #pragma unroll
        for (int j = 0; j < 8; j++) acc[j] = bb;
        for (int k = 0; k < 128; k++) {
            float wv = W2b[k * DD + c];
            #pragma unroll
            for (int j = 0; j < 8; j++) acc[j] += Ys[rg * 8 + j][k] * wv;
        }
        #pragma unroll
        for (int j = 0; j < 8; j++)
            out[(size_t)(a0 + rg * 8 + j) * DD + c] = acc[j];
    }
}

// ---------------- launch ----------------------------------------------------
extern "C" void kernel_launch(void* const* d_in, const int* in_sizes, int n_in,
                              void* d_out, int out_size) {
    const float* ue_hid   = (const float*)d_in[0];
    const float* ap_hid   = (const float*)d_in[1];
    const float* edge_hid = (const float*)d_in[2];
    const int*   src      = (const int*)d_in[3];
    const int*   dst      = (const int*)d_in[4];
    const float* W1a      = (const float*)d_in[5];
    const float* b1a      = (const float*)d_in[6];
    const float* W1b      = (const float*)d_in[7];
    const float* b1b      = (const float*)d_in[8];
    const float* W2a      = (const float*)d_in[9];
    const float* b2a      = (const float*)d_in[10];
    const float* W2b      = (const float*)d_in[11];
    const float* b2b      = (const float*)d_in[12];
    float* out = (float*)d_out;

    cudaFuncSetAttribute(k_main, cudaFuncAttributeMaxDynamicSharedMemorySize, SMEM_MAIN);

    k_hist<<<SCAT_BLOCKS, 256>>>(dst);                                     // 0
    k_scan_prep<<<5, 1024>>>(W1a);                                         // 1
    k_scatter_ueproj<<<SCAT_BLOCKS + UEP_BLOCKS, 256>>>(src, dst,
                                                        ue_hid, W1a, b1a); // 2
    k_main<<<TILES, 256, SMEM_MAIN>>>(edge_hid);                           // 3 (profiled)
    k_final<<<N_AP / 16, 128>>>(ap_hid, W1b, b1b, W2a, b2a, W2b, b2b, out);// 4
}

// round 12
// speedup vs baseline: 1.8384x; 1.0981x over previous
#include <cuda_runtime.h>
#include <cuda_fp16.h>
#include <cstdint>

#define N_UE 100000
#define N_AP 10000
#define N_E  1600000
#define DD   64
#define HH   128
#define SCAT_BLOCKS ((N_E + 255) / 256)     // 6250
#define UEP_BLOCKS  ((N_UE + 63) / 64)      // 1563
#define MAIN_BLOCKS (N_E / 256)             // 6250 (2 tiles of 128 per block)

// ---------------- scratch (device globals; no allocation allowed) ----------
// Invariant: g_cnt == 0 and g_agg == 0 at every kernel_launch entry.
__device__ __half g_ueproj[(size_t)N_UE * HH];   // ue_hid @ W1a[64:] + b1a (fp16)
__device__ float  g_agg[(size_t)N_AP * HH];      // segment_sum(relu(...))
__device__ int    g_cnt[N_AP];
__device__ int    g_cursor[N_AP];
__device__ int4   g_meta[N_E];                   // (edge_idx, src, dst, 0) sorted by dst
__device__ unsigned g_wt_hi2[4096];              // W1a[:64]^T as half2 pairs [n][k2]
__device__ unsigned g_wt_lo2[4096];              // f16 residual plane

__device__ __forceinline__ uint32_t smem_u32(const void* p) {
    uint32_t a;
    asm("{ .reg .u64 t; cvta.to.shared.u64 t, %1; cvt.u32.u64 %0, t; }" : "=r"(a) : "l"(p));
    return a;
}

// ---------------- launch 0: histogram --------------------------------------
__global__ void k_hist(const int* __restrict__ dst) {
    int i = blockIdx.x * 256 + threadIdx.x;
    if (i < N_E) atomicAdd(&g_cnt[dst[i]], 1);
}

// ---------------- launch 1: scan + weight prep ------------------------------
__global__ void k_scan_prep(const float* __restrict__ W1a) {
    if (blockIdx.x == 0) {
        __shared__ int buf[1024];
        int t = threadIdx.x;
        int local[16];
        int s = 0;
        if (t < 625) {
            #pragma unroll
            for (int j = 0; j < 16; j++) { local[j] = s; s += g_cnt[t * 16 + j]; }
        }
        buf[t] = s;
        __syncthreads();
        int own = s;
        for (int off = 1; off < 1024; off <<= 1) {
            int v = 0;
            if (t >= off) v = buf[t - off];
            __syncthreads();
            buf[t] += v;
            __syncthreads();
        }
        int excl = buf[t] - own;
        if (t < 625) {
            #pragma unroll
            for (int j = 0; j < 16; j++) g_cursor[t * 16 + j] = excl + local[j];
        }
    } else {
        int j = (blockIdx.x - 1) * 1024 + threadIdx.x;   // 4096 half2 pairs
        if (j < 4096) {
            int n = j >> 5, k2 = j & 31;                 // pair covers k = 2*k2, 2*k2+1
            float v0 = W1a[(k2 * 2) * HH + n];           // Wt[n][k] = W1a[k][n], k<64
            float v1 = W1a[(k2 * 2 + 1) * HH + n];
            __half2 h = __floats2half2_rn(v0, v1);
            float2 f = __half22float2(h);
            __half2 lo = __floats2half2_rn(v0 - f.x, v1 - f.y);
            g_wt_hi2[j] = *(unsigned*)&h;
            g_wt_lo2[j] = *(unsigned*)&lo;
        }
    }
}

// ---------------- launch 2: fused scatter + ue projection -------------------
__global__ void __launch_bounds__(256) k_scatter_ueproj(
    const int* __restrict__ src, const int* __restrict__ dst,
    const float* __restrict__ ue_hid, const float* __restrict__ W1a,
    const float* __restrict__ b1a)
{
    __shared__ float us[64][64];
    int t = threadIdx.x;

    if (blockIdx.x < SCAT_BLOCKS) {
        int i = blockIdx.x * 256 + t;
        if (i < N_E) {
            int d = dst[i];
            int p = atomicAdd(&g_cursor[d], 1);
            g_meta[p] = make_int4(i, src[i], d, 0);
        }
        return;
    }

    int rbase = (blockIdx.x - SCAT_BLOCKS) * 64;

    for (int f = t; f < 1024; f += 256) {
        int row = f >> 4, c4 = f & 15;
        float4 v = make_float4(0.f, 0.f, 0.f, 0.f);
        if (rbase + row < N_UE)
            v = *(const float4*)(ue_hid + (size_t)(rbase + row) * DD + c4 * 4);
        *(float4*)(&us[row][c4 * 4]) = v;
    }

    int c = t & 127;
    int rh = t >> 7;
    float wc[64];
    #pragma unroll 8
    for (int k = 0; k < 64; k++) wc[k] = W1a[(64 + k) * HH + c];
    float bb = b1a[c];
    __syncthreads();

    for (int i = 0; i < 32; i++) {
        int r = rh * 32 + i;
        int gr = rbase + r;
        if (gr >= N_UE) break;          // uniform per warp
        float acc = bb;
        #pragma unroll
        for (int k4 = 0; k4 < 16; k4++) {
            float4 u4 = *(const float4*)(&us[r][k4 * 4]);
            acc += u4.x * wc[k4 * 4 + 0];
            acc += u4.y * wc[k4 * 4 + 1];
            acc += u4.z * wc[k4 * 4 + 2];
            acc += u4.w * wc[k4 * 4 + 3];
        }
        g_ueproj[(size_t)gr * HH + c] = __float2half(acc);
    }
}

// ---------------- launch 3: main edge kernel (PROFILED INDEX) ---------------
__device__ __forceinline__ void mma_f16(float c[4],
    unsigned a0, unsigned a1, unsigned a2, unsigned a3,
    unsigned b0, unsigned b1)
{
    asm volatile(
        "mma.sync.aligned.m16n8k16.row.col.f32.f16.f16.f32 "
        "{%0,%1,%2,%3}, {%4,%5,%6,%7}, {%8,%9}, {%0,%1,%2,%3};\n"
        : "+f"(c[0]), "+f"(c[1]), "+f"(c[2]), "+f"(c[3])
        : "r"(a0), "r"(a1), "r"(a2), "r"(a3), "r"(b0), "r"(b1));
}

#define LDM4(r0, r1, r2, r3, addr)                                              \
    asm volatile("ldmatrix.sync.aligned.m8n8.x4.shared.b16 {%0,%1,%2,%3}, [%4];" \
                 : "=r"(r0), "=r"(r1), "=r"(r2), "=r"(r3) : "r"(addr))

#define ASTR 72                          // padded smem stride (f16 elems)
#define HSTRH 136                        // Hs stride in halves (conflict-free)
// layout: Ah[128][72] | Bh[128][72] | Bl[128][72] | Hs[128][136] (separate!)
#define SMEM_A  0
#define SMEM_BH (128 * ASTR * 2)
#define SMEM_BL (2 * 128 * ASTR * 2)
#define SMEM_HS (3 * 128 * ASTR * 2)
#define SMEM_MAIN (SMEM_HS + 128 * HSTRH * 2)   // 55296 + 34816 = 90112 B

__global__ void __launch_bounds__(256, 2) k_main(const float* __restrict__ edge_hid)
{
    extern __shared__ char sraw[];
    __half* Ah = (__half*)(sraw + SMEM_A);
    __half* Bh = (__half*)(sraw + SMEM_BH);
    __half* Bl = (__half*)(sraw + SMEM_BL);
    __half2* Hs2 = (__half2*)(sraw + SMEM_HS);
    __shared__ int s_src[128];
    __shared__ int s_dst[128];

    int t = threadIdx.x;
    int w = t >> 5, l = t & 31;
    int wr = w & 3, wc = w >> 2;         // warp tile: rows [32wr,32wr+32) x cols [64wc,64wc+64)
    int g = l >> 2, q4 = l & 3;
    int lm = l >> 3, lr = l & 7;

    // stage weights ONCE per block (reused by both tiles)
    for (int j = t; j < 4096; j += 256) {
        int n = j >> 5, k2 = j & 31;
        *(unsigned*)(Bh + n * ASTR + k2 * 2) = g_wt_hi2[j];
        *(unsigned*)(Bl + n * ASTR + k2 * 2) = g_wt_lo2[j];
    }

    // ldmatrix lane addresses
    // A: for m-tile mt, rows 32wr+16mt + (lm&1)*8 + lr, k-col block (lm>>1)*8
    uint32_t aA0 = smem_u32(Ah) + (uint32_t)(((32 * wr + (lm & 1) * 8 + lr) * ASTR
                                              + (lm >> 1) * 8) * 2);
    uint32_t aA1 = aA0 + 16 * ASTR * 2;
    // B: warp's n-base 64wc; within: m0/m1 = n rows +0..8 @k0/k8, m2/m3 = +8..16
    uint32_t bOff = (uint32_t)((((lm >> 1) * 8 + lr) * ASTR + (lm & 1) * 8) * 2);
    uint32_t aBh = smem_u32(Bh) + (uint32_t)(64 * wc * ASTR * 2) + bOff;
    uint32_t aBl = smem_u32(Bl) + (uint32_t)(64 * wc * ASTR * 2) + bOff;

    #pragma unroll 1
    for (int it = 0; it < 2; it++) {
        int base = blockIdx.x * 256 + it * 128;

        __syncthreads();   // weights staged (it0) / prev reduce done (it1)

        // meta -> smem
        if (t < 128) {
            int4 m = g_meta[base + t];
            s_src[t] = m.y;
            s_dst[t] = m.z;
        }

        // gather + convert 128 edge rows to f16 (row = t>>1, half = t&1)
        {
            int row = t >> 1, half = t & 1;
            int e = g_meta[base + row].x;
            const float4* src4 = (const float4*)(edge_hid + (size_t)e * DD + half * 32);
            int sb = row * ASTR + half * 32;
            #pragma unroll
            for (int q = 0; q < 8; q++) {
                float4 v = src4[q];
                __half2 h01 = __floats2half2_rn(v.x, v.y);
                __half2 h23 = __floats2half2_rn(v.z, v.w);
                uint2 pk = make_uint2(*(unsigned*)&h01, *(unsigned*)&h23);
                *(uint2*)(Ah + sb + q * 4) = pk;      // STS.64
            }
        }
        __syncthreads();

        float C[2][8][4];
        #pragma unroll
        for (int mt = 0; mt < 2; mt++)
            #pragma unroll
            for (int nf = 0; nf < 8; nf++)
                { C[mt][nf][0] = C[mt][nf][1] = C[mt][nf][2] = C[mt][nf][3] = 0.f; }

        #pragma unroll
        for (int kt = 0; kt < 4; kt++) {
            unsigned a0, a1, a2, a3, a4, a5, a6, a7;
            LDM4(a0, a1, a2, a3, aA0 + kt * 32);
            LDM4(a4, a5, a6, a7, aA1 + kt * 32);
            #pragma unroll
            for (int pp = 0; pp < 4; pp++) {          // n-tiles 2pp, 2pp+1
                unsigned h0, h1, h2, h3, l0, l1, l2, l3;
                uint32_t o = (uint32_t)(16 * pp * ASTR * 2) + kt * 32;
                LDM4(h0, h1, h2, h3, aBh + o);
                LDM4(l0, l1, l2, l3, aBl + o);
                // hi plane first: RAW distance 4 before lo revisits each C
                mma_f16(C[0][2 * pp],     a0, a1, a2, a3, h0, h1);
                mma_f16(C[0][2 * pp + 1], a0, a1, a2, a3, h2, h3);
                mma_f16(C[1][2 * pp],     a4, a5, a6, a7, h0, h1);
                mma_f16(C[1][2 * pp + 1], a4, a5, a6, a7, h2, h3);
                mma_f16(C[0][2 * pp],     a0, a1, a2, a3, l0, l1);
                mma_f16(C[0][2 * pp + 1], a0, a1, a2, a3, l2, l3);
                mma_f16(C[1][2 * pp],     a4, a5, a6, a7, l0, l1);
                mma_f16(C[1][2 * pp + 1], a4, a5, a6, a7, l2, l3);
            }
        }

        // epilogue: + ue_proj[src] (f16 gather), relu, stage f16 to Hs
        // (Hs disjoint from A/B: no barrier needed after mma)
        {
            int r0 = 32 * wr + g;                     // rows r0, r0+8, r0+16, r0+24
            const __half* up[4];
            #pragma unroll
            for (int rr = 0; rr < 4; rr++)
                up[rr] = g_ueproj + (size_t)s_src[r0 + rr * 8] * HH;
            #pragma unroll
            for (int mt = 0; mt < 2; mt++) {
                #pragma unroll
                for (int nf = 0; nf < 8; nf++) {
                    int c0 = 64 * wc + 8 * nf + q4 * 2;
                    float2 u0 = __half22float2(*(const __half2*)(up[mt * 2] + c0));
                    float2 u1 = __half22float2(*(const __half2*)(up[mt * 2 + 1] + c0));
                    __half2 v0 = __floats2half2_rn(fmaxf(C[mt][nf][0] + u0.x, 0.f),
                                                   fmaxf(C[mt][nf][1] + u0.y, 0.f));
                    __half2 v1 = __floats2half2_rn(fmaxf(C[mt][nf][2] + u1.x, 0.f),
                                                   fmaxf(C[mt][nf][3] + u1.y, 0.f));
                    int rA = r0 + mt * 16;
                    Hs2[rA * (HSTRH / 2) + (c0 >> 1)] = v0;
                    Hs2[(rA + 8) * (HSTRH / 2) + (c0 >> 1)] = v1;
                }
            }
        }
        __syncthreads();

        // segmented reduce over sorted dst: 4 row-quarters x 64 half2-cols
        {
            int c2 = t & 63, qr = t >> 6;
            int r0 = qr * 32;
            float2 acc = make_float2(0.f, 0.f);
            int prev = s_dst[r0];
            #pragma unroll 4
            for (int i = 0; i < 32; i++) {
                int r = r0 + i;
                int d = s_dst[r];
                if (d != prev) {
                    atomicAdd(&g_agg[(size_t)prev * HH + c2 * 2], acc.x);
                    atomicAdd(&g_agg[(size_t)prev * HH + c2 * 2 + 1], acc.y);
                    acc.x = 0.f; acc.y = 0.f; prev = d;
                }
                float2 hv = __half22float2(Hs2[r * (HSTRH / 2) + c2]);
                acc.x += hv.x;
                acc.y += hv.y;
            }
            atomicAdd(&g_agg[(size_t)prev * HH + c2 * 2], acc.x);
            atomicAdd(&g_agg[(size_t)prev * HH + c2 * 2 + 1], acc.y);
        }
    }
}

// ---------------- launch 4: final AP MLP + scratch cleanup ------------------
__global__ void __launch_bounds__(128) k_final(
    const float* __restrict__ ap_hid,
    const float* __restrict__ W1b, const float* __restrict__ b1b,
    const float* __restrict__ W2a, const float* __restrict__ b2a,
    const float* __restrict__ W2b, const float* __restrict__ b2b,
    float* __restrict__ out)
{
    __shared__ float Ss[16][128];
    __shared__ float Zs[16][192];
    __shared__ float Ys[16][128];
    __shared__ float sdeg[16];

    int t = threadIdx.x;
    int a0 = blockIdx.x * 16;

    for (int i = t; i < 16 * 128; i += 128)
        Ss[i >> 7][i & 127] = g_agg[(size_t)a0 * HH + i];
    if (t < 16) sdeg[t] = (float)g_cnt[a0 + t];
    for (int i = t; i < 16 * 64; i += 128)
        Zs[i >> 6][i & 63] = ap_hid[(size_t)a0 * DD + i];
    __syncthreads();

    // restore scratch invariant for the next kernel_launch call
    for (int i = t; i < 16 * 128; i += 128)
        g_agg[(size_t)a0 * HH + i] = 0.f;
    if (t < 16) g_cnt[a0 + t] = 0;

    // stage 1: Zs[r][64+c] = deg[r]*b1b[c] + sum_k Ss[r][k]*W1b[k][c]
    {
        int c = t;
        float acc[16];
        float bb = b1b[c];
        #pragma unroll
        for (int r = 0; r < 16; r++) acc[r] = sdeg[r] * bb;
        for (int k = 0; k < 128; k++) {
            float wv = W1b[k * HH + c];
            #pragma unroll
            for (int r = 0; r < 16; r++) acc[r] += Ss[r][k] * wv;
        }
        #pragma unroll
        for (int r = 0; r < 16; r++) Zs[r][64 + c] = acc[r];
    }
    __syncthreads();

    // stage 2: Ys = relu(Zs @ W2a + b2a)
    {
        int c = t;
        float acc[16];
        float bb = b2a[c];
        #pragma unroll
        for (int r = 0; r < 16; r++) acc[r] = bb;
        for (int k = 0; k < 192; k++) {
            float wv = W2a[k * HH + c];
            #pragma unroll
            for (int r = 0; r < 16; r++) acc[r] += Zs[r][k] * wv;
        }
        #pragma unroll
        for (int r = 0; r < 16; r++) Ys[r][c] = fmaxf(acc[r], 0.f);
    }
    __syncthreads();

    // stage 3: out = Ys @ W2b + b2b
    {
        int c = t & 63, rg = t >> 6;
        float acc[8];
        float bb = b2b[c];
        #pragma unroll
        for (int j = 0; j < 8; j++) acc[j] = bb;
        for (int k = 0; k < 128; k++) {
            float wv = W2b[k * DD + c];
            #pragma unroll
            for (int j = 0; j < 8; j++) acc[j] += Ys[rg * 8 + j][k] * wv;
        }
        #pragma unroll
        for (int j = 0; j < 8; j++)
            out[(size_t)(a0 + rg * 8 + j) * DD + c] = acc[j];
    }
}

// ---------------- launch ----------------------------------------------------
extern "C" void kernel_launch(void* const* d_in, const int* in_sizes, int n_in,
                              void* d_out, int out_size) {
    const float* ue_hid   = (const float*)d_in[0];
    const float* ap_hid   = (const float*)d_in[1];
    const float* edge_hid = (const float*)d_in[2];
    const int*   src      = (const int*)d_in[3];
    const int*   dst      = (const int*)d_in[4];
    const float* W1a      = (const float*)d_in[5];
    const float* b1a      = (const float*)d_in[6];
    const float* W1b      = (const float*)d_in[7];
    const float* b1b      = (const float*)d_in[8];
    const float* W2a      = (const float*)d_in[9];
    const float* b2a      = (const float*)d_in[10];
    const float* W2b      = (const float*)d_in[11];
    const float* b2b      = (const float*)d_in[12];
    float* out = (float*)d_out;

    cudaFuncSetAttribute(k_main, cudaFuncAttributeMaxDynamicSharedMemorySize, SMEM_MAIN);

    k_hist<<<SCAT_BLOCKS, 256>>>(dst);                                     // 0
    k_scan_prep<<<5, 1024>>>(W1a);                                         // 1
    k_scatter_ueproj<<<SCAT_BLOCKS + UEP_BLOCKS, 256>>>(src, dst,
                                                        ue_hid, W1a, b1a); // 2
    k_main<<<MAIN_BLOCKS, 256, SMEM_MAIN>>>(edge_hid);                     // 3 (profiled)
    k_final<<<N_AP / 16, 128>>>(ap_hid, W1b, b1b, W2a, b2a, W2b, b2b, out);// 4
}

// round 14
// speedup vs baseline: 2.1200x; 1.1532x over previous
#include <cuda_runtime.h>
#include <cuda_fp16.h>
#include <cstdint>

#define N_UE 100000
#define N_AP 10000
#define N_E  1600000
#define DD   64
#define HH   128
#define SCAT_BLOCKS ((N_E + 255) / 256)     // 6250
#define UEP_BLOCKS  ((N_UE + 63) / 64)      // 1563
#define MAIN_BLOCKS (N_E / 256)             // 6250 (2 tiles of 128 per block)

// ---------------- scratch (device globals; no allocation allowed) ----------
// Invariant: g_cnt == 0 and g_agg == 0 at every kernel_launch entry.
__device__ __half g_ueproj[(size_t)N_UE * HH];   // ue_hid @ W1a[64:] + b1a (fp16)
__device__ float  g_agg[(size_t)N_AP * HH];      // segment_sum(relu(...))
__device__ int    g_cnt[N_AP];
__device__ int    g_cursor[N_AP];
__device__ int4   g_meta[N_E];                   // (edge_idx, src, dst, 0) sorted by dst
__device__ unsigned g_wt[4096];                  // W1a[:64]^T as half2 pairs [n][k2]

__device__ __forceinline__ uint32_t smem_u32(const void* p) {
    uint32_t a;
    asm("{ .reg .u64 t; cvta.to.shared.u64 t, %1; cvt.u32.u64 %0, t; }" : "=r"(a) : "l"(p));
    return a;
}

// ---------------- launch 0: histogram --------------------------------------
__global__ void k_hist(const int* __restrict__ dst) {
    int i = blockIdx.x * 256 + threadIdx.x;
    if (i < N_E) atomicAdd(&g_cnt[dst[i]], 1);
}

// ---------------- launch 1: scan + weight prep ------------------------------
__global__ void k_scan_prep(const float* __restrict__ W1a) {
    if (blockIdx.x == 0) {
        __shared__ int buf[1024];
        int t = threadIdx.x;
        int local[16];
        int s = 0;
        if (t < 625) {
            #pragma unroll
            for (int j = 0; j < 16; j++) { local[j] = s; s += g_cnt[t * 16 + j]; }
        }
        buf[t] = s;
        __syncthreads();
        int own = s;
        for (int off = 1; off < 1024; off <<= 1) {
            int v = 0;
            if (t >= off) v = buf[t - off];
            __syncthreads();
            buf[t] += v;
            __syncthreads();
        }
        int excl = buf[t] - own;
        if (t < 625) {
            #pragma unroll
            for (int j = 0; j < 16; j++) g_cursor[t * 16 + j] = excl + local[j];
        }
    } else {
        int j = (blockIdx.x - 1) * 1024 + threadIdx.x;   // 4096 half2 pairs
        if (j < 4096) {
            int n = j >> 5, k2 = j & 31;                 // pair covers k = 2*k2, 2*k2+1
            float v0 = W1a[(k2 * 2) * HH + n];           // Wt[n][k] = W1a[k][n], k<64
            float v1 = W1a[(k2 * 2 + 1) * HH + n];
            __half2 h = __floats2half2_rn(v0, v1);
            g_wt[j] = *(unsigned*)&h;
        }
    }
}

// ---------------- launch 2: fused scatter + ue projection -------------------
__global__ void __launch_bounds__(256) k_scatter_ueproj(
    const int* __restrict__ src, const int* __restrict__ dst,
    const float* __restrict__ ue_hid, const float* __restrict__ W1a,
    const float* __restrict__ b1a)
{
    __shared__ float us[64][64];
    int t = threadIdx.x;

    if (blockIdx.x < SCAT_BLOCKS) {
        int i = blockIdx.x * 256 + t;
        if (i < N_E) {
            int d = dst[i];
            int p = atomicAdd(&g_cursor[d], 1);
            g_meta[p] = make_int4(i, src[i], d, 0);
        }
        return;
    }

    int rbase = (blockIdx.x - SCAT_BLOCKS) * 64;

    for (int f = t; f < 1024; f += 256) {
        int row = f >> 4, c4 = f & 15;
        float4 v = make_float4(0.f, 0.f, 0.f, 0.f);
        if (rbase + row < N_UE)
            v = *(const float4*)(ue_hid + (size_t)(rbase + row) * DD + c4 * 4);
        *(float4*)(&us[row][c4 * 4]) = v;
    }

    int c = t & 127;
    int rh = t >> 7;
    float wc[64];
    #pragma unroll 8
    for (int k = 0; k < 64; k++) wc[k] = W1a[(64 + k) * HH + c];
    float bb = b1a[c];
    __syncthreads();

    for (int i = 0; i < 32; i++) {
        int r = rh * 32 + i;
        int gr = rbase + r;
        if (gr >= N_UE) break;          // uniform per warp
        float acc = bb;
        #pragma unroll
        for (int k4 = 0; k4 < 16; k4++) {
            float4 u4 = *(const float4*)(&us[r][k4 * 4]);
            acc += u4.x * wc[k4 * 4 + 0];
            acc += u4.y * wc[k4 * 4 + 1];
            acc += u4.z * wc[k4 * 4 + 2];
            acc += u4.w * wc[k4 * 4 + 3];
        }
        g_ueproj[(size_t)gr * HH + c] = __float2half(acc);
    }
}

// ---------------- launch 3: main edge kernel (PROFILED INDEX) ---------------
__device__ __forceinline__ void mma_f16(float c[4],
    unsigned a0, unsigned a1, unsigned a2, unsigned a3,
    unsigned b0, unsigned b1)
{
    asm volatile(
        "mma.sync.aligned.m16n8k16.row.col.f32.f16.f16.f32 "
        "{%0,%1,%2,%3}, {%4,%5,%6,%7}, {%8,%9}, {%0,%1,%2,%3};\n"
        : "+f"(c[0]), "+f"(c[1]), "+f"(c[2]), "+f"(c[3])
        : "r"(a0), "r"(a1), "r"(a2), "r"(a3), "r"(b0), "r"(b1));
}

#define LDM4(r0, r1, r2, r3, addr)                                              \
    asm volatile("ldmatrix.sync.aligned.m8n8.x4.shared.b16 {%0,%1,%2,%3}, [%4];" \
                 : "=r"(r0), "=r"(r1), "=r"(r2), "=r"(r3) : "r"(addr))

#define ASTR 72                          // padded smem stride (f16 elems)
#define HSTRH 136                        // Hs stride in halves (conflict-free)
// layout: Ah[128][72] | B[128][72] | Hs[128][136]
#define SMEM_A  0
#define SMEM_B  (128 * ASTR * 2)                 // 18432
#define SMEM_HS (2 * 128 * ASTR * 2)             // 36864
#define SMEM_MAIN (SMEM_HS + 128 * HSTRH * 2)    // 71680 B

__global__ void __launch_bounds__(256, 2) k_main(const float* __restrict__ edge_hid)
{
    extern __shared__ char sraw[];
    __half* Ah = (__half*)(sraw + SMEM_A);
    __half* Bs = (__half*)(sraw + SMEM_B);
    __half2* Hs2 = (__half2*)(sraw + SMEM_HS);
    __shared__ int s_src[128];
    __shared__ int s_dst[128];

    int t = threadIdx.x;
    int w = t >> 5, l = t & 31;
    int wr = w & 3, wc = w >> 2;         // warp tile: rows [32wr,+32) x cols [64wc,+64)
    int g = l >> 2, q4 = l & 3;
    int lm = l >> 3, lr = l & 7;

    // stage weights ONCE per block (single f16 plane, uint4-vectorized)
    {
        const uint4* wsrc = (const uint4*)g_wt;
        uint4* wdst = (uint4*)Bs;
        // g_wt is [n][k2] packed densely (32 unsigned per n = 2 uint4 per n)
        for (int j = t; j < 1024; j += 256) {
            int n = j >> 3, q = j & 7;   // 8 uint4 per n? no: 32 unsigned = 8 uint4
            ((uint4*)(Bs + n * ASTR))[q] = wsrc[n * 8 + q];
        }
    }

    // ldmatrix lane addresses
    uint32_t aA0 = smem_u32(Ah) + (uint32_t)(((32 * wr + (lm & 1) * 8 + lr) * ASTR
                                              + (lm >> 1) * 8) * 2);
    uint32_t aA1 = aA0 + 16 * ASTR * 2;
    uint32_t bOff = (uint32_t)((((lm >> 1) * 8 + lr) * ASTR + (lm & 1) * 8) * 2);
    uint32_t aB = smem_u32(Bs) + (uint32_t)(64 * wc * ASTR * 2) + bOff;

    #pragma unroll 1
    for (int it = 0; it < 2; it++) {
        int base = blockIdx.x * 256 + it * 128;

        __syncthreads();   // weights staged (it0) / prev reduce done (it1)

        // meta -> smem
        if (t < 128) {
            int4 m = g_meta[base + t];
            s_src[t] = m.y;
            s_dst[t] = m.z;
        }

        // gather + convert 128 edge rows to f16 (row = t>>1, half = t&1)
        {
            int row = t >> 1, half = t & 1;
            int e = g_meta[base + row].x;
            const float4* src4 = (const float4*)(edge_hid + (size_t)e * DD + half * 32);
            int sb = row * ASTR + half * 32;
            #pragma unroll
            for (int q = 0; q < 8; q += 2) {
                float4 v = src4[q];
                float4 v2 = src4[q + 1];
                __half2 h01 = __floats2half2_rn(v.x, v.y);
                __half2 h23 = __floats2half2_rn(v.z, v.w);
                __half2 h45 = __floats2half2_rn(v2.x, v2.y);
                __half2 h67 = __floats2half2_rn(v2.z, v2.w);
                uint4 pk = make_uint4(*(unsigned*)&h01, *(unsigned*)&h23,
                                      *(unsigned*)&h45, *(unsigned*)&h67);
                *(uint4*)(Ah + sb + q * 4) = pk;      // STS.128 (16B aligned)
            }
        }
        __syncthreads();

        float C[2][8][4];
        #pragma unroll
        for (int mt = 0; mt < 2; mt++)
            #pragma unroll
            for (int nf = 0; nf < 8; nf++)
                { C[mt][nf][0] = C[mt][nf][1] = C[mt][nf][2] = C[mt][nf][3] = 0.f; }

        #pragma unroll
        for (int kt = 0; kt < 4; kt++) {
            unsigned a0, a1, a2, a3, a4, a5, a6, a7;
            LDM4(a0, a1, a2, a3, aA0 + kt * 32);
            LDM4(a4, a5, a6, a7, aA1 + kt * 32);
            #pragma unroll
            for (int pp = 0; pp < 4; pp++) {          // n-tiles 2pp, 2pp+1
                unsigned b0, b1, b2, b3;
                LDM4(b0, b1, b2, b3, aB + (uint32_t)(16 * pp * ASTR * 2) + kt * 32);
                mma_f16(C[0][2 * pp],     a0, a1, a2, a3, b0, b1);
                mma_f16(C[0][2 * pp + 1], a0, a1, a2, a3, b2, b3);
                mma_f16(C[1][2 * pp],     a4, a5, a6, a7, b0, b1);
                mma_f16(C[1][2 * pp + 1], a4, a5, a6, a7, b2, b3);
            }
        }

        // epilogue: + ue_proj[src] (f16 gather), relu, stage f16 to Hs
        {
            int r0 = 32 * wr + g;
            const __half* up[4];
            #pragma unroll
            for (int rr = 0; rr < 4; rr++)
                up[rr] = g_ueproj + (size_t)s_src[r0 + rr * 8] * HH;
            #pragma unroll
            for (int mt = 0; mt < 2; mt++) {
                #pragma unroll
                for (int nf = 0; nf < 8; nf++) {
                    int c0 = 64 * wc + 8 * nf + q4 * 2;
                    float2 u0 = __half22float2(*(const __half2*)(up[mt * 2] + c0));
                    float2 u1 = __half22float2(*(const __half2*)(up[mt * 2 + 1] + c0));
                    __half2 v0 = __floats2half2_rn(fmaxf(C[mt][nf][0] + u0.x, 0.f),
                                                   fmaxf(C[mt][nf][1] + u0.y, 0.f));
                    __half2 v1 = __floats2half2_rn(fmaxf(C[mt][nf][2] + u1.x, 0.f),
                                                   fmaxf(C[mt][nf][3] + u1.y, 0.f));
                    int rA = r0 + mt * 16;
                    Hs2[rA * (HSTRH / 2) + (c0 >> 1)] = v0;
                    Hs2[(rA + 8) * (HSTRH / 2) + (c0 >> 1)] = v1;
                }
            }
        }
        __syncthreads();

        // segmented reduce over sorted dst: 8 strips of 16 rows x 32 LDS.64 lanes
        {
            int c4 = t & 31, qr = t >> 5;     // lane covers float cols [4c4, 4c4+4)
            int r0 = qr * 16;
            float acc0 = 0.f, acc1 = 0.f, acc2 = 0.f, acc3 = 0.f;
            int prev = s_dst[r0];
            float* aggp = g_agg + (size_t)prev * HH + c4 * 4;
            #pragma unroll 4
            for (int i = 0; i < 16; i++) {
                int r = r0 + i;
                int d = s_dst[r];
                if (d != prev) {
                    atomicAdd(aggp + 0, acc0);
                    atomicAdd(aggp + 1, acc1);
                    atomicAdd(aggp + 2, acc2);
                    atomicAdd(aggp + 3, acc3);
                    acc0 = acc1 = acc2 = acc3 = 0.f;
                    prev = d;
                    aggp = g_agg + (size_t)prev * HH + c4 * 4;
                }
                uint2 pk = *(const uint2*)(Hs2 + r * (HSTRH / 2) + c4 * 2);  // LDS.64
                float2 hv0 = __half22float2(*(__half2*)&pk.x);
                float2 hv1 = __half22float2(*(__half2*)&pk.y);
                acc0 += hv0.x; acc1 += hv0.y; acc2 += hv1.x; acc3 += hv1.y;
            }
            atomicAdd(aggp + 0, acc0);
            atomicAdd(aggp + 1, acc1);
            atomicAdd(aggp + 2, acc2);
            atomicAdd(aggp + 3, acc3);
        }
    }
}

// ---------------- launch 4: final AP MLP + scratch cleanup ------------------
__global__ void __launch_bounds__(128) k_final(
    const float* __restrict__ ap_hid,
    const float* __restrict__ W1b, const float* __restrict__ b1b,
    const float* __restrict__ W2a, const float* __restrict__ b2a,
    const float* __restrict__ W2b, const float* __restrict__ b2b,
    float* __restrict__ out)
{
    __shared__ float Ss[16][128];
    __shared__ float Zs[16][192];
    __shared__ float Ys[16][128];
    __shared__ float sdeg[16];

    int t = threadIdx.x;
    int a0 = blockIdx.x * 16;

    for (int i = t; i < 16 * 128; i += 128)
        Ss[i >> 7][i & 127] = g_agg[(size_t)a0 * HH + i];
    if (t < 16) sdeg[t] = (float)g_cnt[a0 + t];
    for (int i = t; i < 16 * 64; i += 128)
        Zs[i >> 6][i & 63] = ap_hid[(size_t)a0 * DD + i];
    __syncthreads();

    // restore scratch invariant for the next kernel_launch call
    for (int i = t; i < 16 * 128; i += 128)
        g_agg[(size_t)a0 * HH + i] = 0.f;
    if (t < 16) g_cnt[a0 + t] = 0;

    // stage 1: Zs[r][64+c] = deg[r]*b1b[c] + sum_k Ss[r][k]*W1b[k][c]
    {
        int c = t;
        float acc[16];
        float bb = b1b[c];
        #pragma unroll
        for (int r = 0; r < 16; r++) acc[r] = sdeg[r] * bb;
        for (int k = 0; k < 128; k++) {
            float wv = W1b[k * HH + c];
            #pragma unroll
            for (int r = 0; r < 16; r++) acc[r] += Ss[r][k] * wv;
        }
        #pragma unroll
        for (int r = 0; r < 16; r++) Zs[r][64 + c] = acc[r];
    }
    __syncthreads();

    // stage 2: Ys = relu(Zs @ W2a + b2a)
    {
        int c = t;
        float acc[16];
        float bb = b2a[c];
        #pragma unroll
        for (int r = 0; r < 16; r++) acc[r] = bb;
        for (int k = 0; k < 192; k++) {
            float wv = W2a[k * HH + c];
            #pragma unroll
            for (int r = 0; r < 16; r++) acc[r] += Zs[r][k] * wv;
        }
        #pragma unroll
        for (int r = 0; r < 16; r++) Ys[r][c] = fmaxf(acc[r], 0.f);
    }
    __syncthreads();

    // stage 3: out = Ys @ W2b + b2b
    {
        int c = t & 63, rg = t >> 6;
        float acc[8];
        float bb = b2b[c];
        #pragma unroll
        for (int j = 0; j < 8; j++) acc[j] = bb;
        for (int k = 0; k < 128; k++) {
            float wv = W2b[k * DD + c];
            #pragma unroll
            for (int j = 0; j < 8; j++) acc[j] += Ys[rg * 8 + j][k] * wv;
        }
        #pragma unroll
        for (int j = 0; j < 8; j++)
            out[(size_t)(a0 + rg * 8 + j) * DD + c] = acc[j];
    }
}

// ---------------- launch ----------------------------------------------------
extern "C" void kernel_launch(void* const* d_in, const int* in_sizes, int n_in,
                              void* d_out, int out_size) {
    const float* ue_hid   = (const float*)d_in[0];
    const float* ap_hid   = (const float*)d_in[1];
    const float* edge_hid = (const float*)d_in[2];
    const int*   src      = (const int*)d_in[3];
    const int*   dst      = (const int*)d_in[4];
    const float* W1a      = (const float*)d_in[5];
    const float* b1a      = (const float*)d_in[6];
    const float* W1b      = (const float*)d_in[7];
    const float* b1b      = (const float*)d_in[8];
    const float* W2a      = (const float*)d_in[9];
    const float* b2a      = (const float*)d_in[10];
    const float* W2b      = (const float*)d_in[11];
    const float* b2b      = (const float*)d_in[12];
    float* out = (float*)d_out;

    cudaFuncSetAttribute(k_main, cudaFuncAttributeMaxDynamicSharedMemorySize, SMEM_MAIN);

    k_hist<<<SCAT_BLOCKS, 256>>>(dst);                                     // 0
    k_scan_prep<<<5, 1024>>>(W1a);                                         // 1
    k_scatter_ueproj<<<SCAT_BLOCKS + UEP_BLOCKS, 256>>>(src, dst,
                                                        ue_hid, W1a, b1a); // 2
    k_main<<<MAIN_BLOCKS, 256, SMEM_MAIN>>>(edge_hid);                     // 3 (profiled)
    k_final<<<N_AP / 16, 128>>>(ap_hid, W1b, b1b, W2a, b2a, W2b, b2b, out);// 4
}